// round 1
// baseline (speedup 1.0000x reference)
#include <cuda_runtime.h>
#include <cuda_bf16.h>
#include <math.h>

// Problem constants
#define BATCH 2
#define SEQ   1024
#define HID   5120
#define NHEAD 40
#define HDIM  128
#define QKV_N (3*HID)          // 15360
#define MROWS (BATCH*SEQ)      // 2048

// Scratch (static device allocations are the sanctioned mechanism)
__device__ float g_qkv[(size_t)MROWS * QKV_N];   // [2048, 15360]
__device__ float g_attn[(size_t)MROWS * HID];    // [2048, 5120]

// ---------------------------------------------------------------------------
// SGEMM: C[M,N] = A[M,K] @ B[N,K]^T   (both row-major, B is weight [out,in])
// 128x128 tile, TK=16, 256 threads, 8x8 microtile per thread.
// ---------------------------------------------------------------------------
#define TM 128
#define TN 128
#define TK 16

__global__ __launch_bounds__(256)
void sgemm_nt(const float* __restrict__ A, const float* __restrict__ B,
              float* __restrict__ C, int M, int N, int K)
{
    __shared__ float As[TK][TM];
    __shared__ float Bs[TK][TN];

    const int tid = threadIdx.x;
    const int tx = tid & 15;
    const int ty = tid >> 4;
    const int m0 = blockIdx.y * TM;
    const int n0 = blockIdx.x * TN;

    float acc[8][8];
#pragma unroll
    for (int r = 0; r < 8; r++)
#pragma unroll
        for (int c = 0; c < 8; c++) acc[r][c] = 0.f;

    for (int k0 = 0; k0 < K; k0 += TK) {
        // Load A tile (128x16) and B tile (128x16), store k-major in smem.
#pragma unroll
        for (int i = 0; i < 2; i++) {
            int f   = tid + i * 256;      // 0..511 float4 slots
            int row = f >> 2;             // 0..127
            int c4  = f & 3;              // 0..3
            float4 va = *(const float4*)(A + (size_t)(m0 + row) * K + k0 + c4 * 4);
            As[c4*4+0][row] = va.x; As[c4*4+1][row] = va.y;
            As[c4*4+2][row] = va.z; As[c4*4+3][row] = va.w;
            float4 vb = *(const float4*)(B + (size_t)(n0 + row) * K + k0 + c4 * 4);
            Bs[c4*4+0][row] = vb.x; Bs[c4*4+1][row] = vb.y;
            Bs[c4*4+2][row] = vb.z; Bs[c4*4+3][row] = vb.w;
        }
        __syncthreads();

#pragma unroll
        for (int kk = 0; kk < TK; kk++) {
            float a[8], b[8];
            *(float4*)&a[0] = *(const float4*)&As[kk][ty*8];
            *(float4*)&a[4] = *(const float4*)&As[kk][ty*8+4];
            *(float4*)&b[0] = *(const float4*)&Bs[kk][tx*8];
            *(float4*)&b[4] = *(const float4*)&Bs[kk][tx*8+4];
#pragma unroll
            for (int r = 0; r < 8; r++)
#pragma unroll
                for (int c = 0; c < 8; c++)
                    acc[r][c] = fmaf(a[r], b[c], acc[r][c]);
        }
        __syncthreads();
    }

#pragma unroll
    for (int r = 0; r < 8; r++) {
        float* crow = C + (size_t)(m0 + ty*8 + r) * N + n0 + tx*8;
        float4 v0 = make_float4(acc[r][0], acc[r][1], acc[r][2], acc[r][3]);
        float4 v1 = make_float4(acc[r][4], acc[r][5], acc[r][6], acc[r][7]);
        *(float4*)(crow)     = v0;
        *(float4*)(crow + 4) = v1;
    }
}

// ---------------------------------------------------------------------------
// Flash-style attention, fp32, 64 q-rows x 64 k-rows tiles, online softmax.
// qkv layout: [2048, 15360]; q at col h*128, k at 5120+h*128, v at 10240+h*128.
// mask: [NHEAD, SEQ, SEQ] fp32 (causal -inf + alibi already baked in).
// out (g_attn): [2048, 5120] with head-interleaved columns.
// ---------------------------------------------------------------------------
#define QT 64
#define KT 64
#define DSTR 132           // padded row stride for q/k/v tiles (floats)
#define PSTR 68            // padded row stride for prob tile

#define ATTN_SMEM_FLOATS (3*QT*DSTR + QT*PSTR)
#define ATTN_SMEM_BYTES  (ATTN_SMEM_FLOATS * 4)

__global__ __launch_bounds__(256)
void attn_kernel(const float* __restrict__ qkv, const float* __restrict__ mask,
                 float* __restrict__ out)
{
    const int qt = blockIdx.x;     // 0..15
    const int h  = blockIdx.y;     // 0..39
    const int b  = blockIdx.z;     // 0..1

    extern __shared__ float sm[];
    float* q_s = sm;                       // [QT][DSTR]
    float* k_s = q_s + QT * DSTR;          // [KT][DSTR]
    float* v_s = k_s + QT * DSTR;          // [KT][DSTR]
    float* p_s = v_s + QT * DSTR;          // [QT][PSTR]

    const int tid = threadIdx.x;
    const int tx = tid & 15;               // col group
    const int ty = tid >> 4;               // row group
    const int q0 = qt * QT;

    const size_t qkv_stride = QKV_N;
    const float scale = 0.08838834764831845f;   // 1/sqrt(128)

    // Load Q tile: 64x128 floats = 2048 float4, 8 per thread
#pragma unroll
    for (int i = 0; i < 8; i++) {
        int f = tid + i * 256;
        int row = f >> 5;          // 32 float4 per row
        int c4  = f & 31;
        const float* src = qkv + (size_t)(b*SEQ + q0 + row) * qkv_stride + h*HDIM + c4*4;
        *(float4*)&q_s[row*DSTR + c4*4] = *(const float4*)src;
    }

    float m[4], l[4], o[4][8];
#pragma unroll
    for (int r = 0; r < 4; r++) {
        m[r] = -INFINITY; l[r] = 0.f;
#pragma unroll
        for (int c = 0; c < 8; c++) o[r][c] = 0.f;
    }

    for (int kt = 0; kt <= qt; kt++) {
        const int k0 = kt * KT;
        __syncthreads();   // prior PV done reading k_s/v_s/p_s

        // Load K and V tiles
#pragma unroll
        for (int i = 0; i < 8; i++) {
            int f = tid + i * 256;
            int row = f >> 5;
            int c4  = f & 31;
            const float* ksrc = qkv + (size_t)(b*SEQ + k0 + row) * qkv_stride + HID   + h*HDIM + c4*4;
            const float* vsrc = qkv + (size_t)(b*SEQ + k0 + row) * qkv_stride + 2*HID + h*HDIM + c4*4;
            *(float4*)&k_s[row*DSTR + c4*4] = *(const float4*)ksrc;
            *(float4*)&v_s[row*DSTR + c4*4] = *(const float4*)vsrc;
        }
        __syncthreads();

        // S tile: rows ty*4+r, cols tx*4+c
        float sacc[4][4];
#pragma unroll
        for (int r = 0; r < 4; r++)
#pragma unroll
            for (int c = 0; c < 4; c++) sacc[r][c] = 0.f;

        for (int d = 0; d < HDIM; d += 4) {
            float4 a[4], bb[4];
#pragma unroll
            for (int r = 0; r < 4; r++) a[r]  = *(const float4*)&q_s[(ty*4+r)*DSTR + d];
#pragma unroll
            for (int c = 0; c < 4; c++) bb[c] = *(const float4*)&k_s[(tx*4+c)*DSTR + d];
#pragma unroll
            for (int r = 0; r < 4; r++)
#pragma unroll
                for (int c = 0; c < 4; c++) {
                    sacc[r][c] = fmaf(a[r].x, bb[c].x, sacc[r][c]);
                    sacc[r][c] = fmaf(a[r].y, bb[c].y, sacc[r][c]);
                    sacc[r][c] = fmaf(a[r].z, bb[c].z, sacc[r][c]);
                    sacc[r][c] = fmaf(a[r].w, bb[c].w, sacc[r][c]);
                }
        }

        // scale + mask, online softmax update
#pragma unroll
        for (int r = 0; r < 4; r++) {
            const int qrow = q0 + ty*4 + r;
            const float* mrow = mask + ((size_t)h * SEQ + qrow) * SEQ + k0 + tx*4;
            float4 mk = *(const float4*)mrow;
            float s0 = sacc[r][0]*scale + mk.x;
            float s1 = sacc[r][1]*scale + mk.y;
            float s2 = sacc[r][2]*scale + mk.z;
            float s3 = sacc[r][3]*scale + mk.w;
            // clamp like reference (avoids -inf-(-inf) pathologies; same softmax result)
            s0 = fmaxf(s0, -3.3e38f); s1 = fmaxf(s1, -3.3e38f);
            s2 = fmaxf(s2, -3.3e38f); s3 = fmaxf(s3, -3.3e38f);

            float rm = fmaxf(fmaxf(s0, s1), fmaxf(s2, s3));
#pragma unroll
            for (int off = 8; off >= 1; off >>= 1)
                rm = fmaxf(rm, __shfl_xor_sync(0xffffffffu, rm, off, 16));

            float mn = fmaxf(m[r], rm);
            float alpha = __expf(m[r] - mn);

            float p0 = __expf(s0 - mn);
            float p1 = __expf(s1 - mn);
            float p2 = __expf(s2 - mn);
            float p3 = __expf(s3 - mn);
            float* prow = &p_s[(ty*4+r)*PSTR + tx*4];
            prow[0] = p0; prow[1] = p1; prow[2] = p2; prow[3] = p3;

            float ps = p0 + p1 + p2 + p3;
#pragma unroll
            for (int off = 8; off >= 1; off >>= 1)
                ps += __shfl_xor_sync(0xffffffffu, ps, off, 16);

            l[r] = l[r] * alpha + ps;
            m[r] = mn;
#pragma unroll
            for (int c = 0; c < 8; c++) o[r][c] *= alpha;
        }
        __syncthreads();   // p_s fully written

        // PV accumulate: O[rows ty*4+r][cols tx*8..+7]
        for (int j = 0; j < KT; j++) {
            float p0 = p_s[(ty*4+0)*PSTR + j];
            float p1 = p_s[(ty*4+1)*PSTR + j];
            float p2 = p_s[(ty*4+2)*PSTR + j];
            float p3 = p_s[(ty*4+3)*PSTR + j];
            float4 v0 = *(const float4*)&v_s[j*DSTR + tx*8];
            float4 v1 = *(const float4*)&v_s[j*DSTR + tx*8 + 4];
            o[0][0]=fmaf(p0,v0.x,o[0][0]); o[0][1]=fmaf(p0,v0.y,o[0][1]);
            o[0][2]=fmaf(p0,v0.z,o[0][2]); o[0][3]=fmaf(p0,v0.w,o[0][3]);
            o[0][4]=fmaf(p0,v1.x,o[0][4]); o[0][5]=fmaf(p0,v1.y,o[0][5]);
            o[0][6]=fmaf(p0,v1.z,o[0][6]); o[0][7]=fmaf(p0,v1.w,o[0][7]);
            o[1][0]=fmaf(p1,v0.x,o[1][0]); o[1][1]=fmaf(p1,v0.y,o[1][1]);
            o[1][2]=fmaf(p1,v0.z,o[1][2]); o[1][3]=fmaf(p1,v0.w,o[1][3]);
            o[1][4]=fmaf(p1,v1.x,o[1][4]); o[1][5]=fmaf(p1,v1.y,o[1][5]);
            o[1][6]=fmaf(p1,v1.z,o[1][6]); o[1][7]=fmaf(p1,v1.w,o[1][7]);
            o[2][0]=fmaf(p2,v0.x,o[2][0]); o[2][1]=fmaf(p2,v0.y,o[2][1]);
            o[2][2]=fmaf(p2,v0.z,o[2][2]); o[2][3]=fmaf(p2,v0.w,o[2][3]);
            o[2][4]=fmaf(p2,v1.x,o[2][4]); o[2][5]=fmaf(p2,v1.y,o[2][5]);
            o[2][6]=fmaf(p2,v1.z,o[2][6]); o[2][7]=fmaf(p2,v1.w,o[2][7]);
            o[3][0]=fmaf(p3,v0.x,o[3][0]); o[3][1]=fmaf(p3,v0.y,o[3][1]);
            o[3][2]=fmaf(p3,v0.z,o[3][2]); o[3][3]=fmaf(p3,v0.w,o[3][3]);
            o[3][4]=fmaf(p3,v1.x,o[3][4]); o[3][5]=fmaf(p3,v1.y,o[3][5]);
            o[3][6]=fmaf(p3,v1.z,o[3][6]); o[3][7]=fmaf(p3,v1.w,o[3][7]);
        }
    }

    // Normalize and write: g_attn[b*SEQ+q, h*128 + d]
#pragma unroll
    for (int r = 0; r < 4; r++) {
        float inv = 1.0f / l[r];
        float* dst = out + (size_t)(b*SEQ + q0 + ty*4 + r) * HID + h*HDIM + tx*8;
        float4 w0 = make_float4(o[r][0]*inv, o[r][1]*inv, o[r][2]*inv, o[r][3]*inv);
        float4 w1 = make_float4(o[r][4]*inv, o[r][5]*inv, o[r][6]*inv, o[r][7]*inv);
        *(float4*)(dst)     = w0;
        *(float4*)(dst + 4) = w1;
    }
}

// ---------------------------------------------------------------------------
// Launch
// ---------------------------------------------------------------------------
extern "C" void kernel_launch(void* const* d_in, const int* in_sizes, int n_in,
                              void* d_out, int out_size)
{
    const float* hidden = (const float*)d_in[0];   // [2,1024,5120]
    const float* W_pack = (const float*)d_in[1];   // [15360,5120]
    const float* W_o    = (const float*)d_in[2];   // [5120,5120]
    const float* mask   = (const float*)d_in[3];   // [40,1024,1024]
    float* out = (float*)d_out;                    // [2,1024,5120]

    float* qkv;  cudaGetSymbolAddress((void**)&qkv,  g_qkv);
    float* attn; cudaGetSymbolAddress((void**)&attn, g_attn);

    cudaFuncSetAttribute(attn_kernel, cudaFuncAttributeMaxDynamicSharedMemorySize,
                         ATTN_SMEM_BYTES);

    // GEMM1: qkv[2048,15360] = hidden[2048,5120] @ W_pack^T
    sgemm_nt<<<dim3(QKV_N/TN, MROWS/TM), 256>>>(hidden, W_pack, qkv,
                                                MROWS, QKV_N, HID);

    // Attention
    attn_kernel<<<dim3(SEQ/QT, NHEAD, BATCH), 256, ATTN_SMEM_BYTES>>>(qkv, mask, attn);

    // GEMM2: out[2048,5120] = attn[2048,5120] @ W_o^T
    sgemm_nt<<<dim3(HID/TN, MROWS/TM), 256>>>(attn, W_o, out,
                                              MROWS, HID, HID);
}

// round 3
// speedup vs baseline: 1.9190x; 1.9190x over previous
#include <cuda_runtime.h>
#include <cuda_bf16.h>
#include <math.h>
#include <stdint.h>

// Problem constants
#define BATCH 2
#define SEQ   1024
#define HID   5120
#define NHEAD 40
#define HDIM  128
#define QKV_N (3*HID)          // 15360
#define MROWS (BATCH*SEQ)      // 2048

// ---------------------------------------------------------------------------
// Scratch
// ---------------------------------------------------------------------------
__device__ float g_qkv[(size_t)MROWS * QKV_N];   // [2048, 15360]
__device__ float g_attn[(size_t)MROWS * HID];    // [2048, 5120]
__device__ __nv_bfloat16 g_hh[(size_t)MROWS * HID];
__device__ __nv_bfloat16 g_hl[(size_t)MROWS * HID];
__device__ __nv_bfloat16 g_ah[(size_t)MROWS * HID];
__device__ __nv_bfloat16 g_al[(size_t)MROWS * HID];
__device__ __nv_bfloat16 g_wph[(size_t)QKV_N * HID];
__device__ __nv_bfloat16 g_wpl[(size_t)QKV_N * HID];
__device__ __nv_bfloat16 g_woh[(size_t)HID * HID];
__device__ __nv_bfloat16 g_wol[(size_t)HID * HID];

// ---------------------------------------------------------------------------
// PTX helpers (compute_103-safe: sm_80-era instructions only)
// ---------------------------------------------------------------------------
__device__ __forceinline__ uint32_t smem_u32(const void* p) {
    uint32_t a;
    asm("{ .reg .u64 t; cvta.to.shared.u64 t, %1; cvt.u32.u64 %0, t; }"
        : "=r"(a) : "l"(p));
    return a;
}

#define CP_ASYNC16(dst, src) \
    asm volatile("cp.async.cg.shared.global [%0], [%1], 16;" \
        :: "r"(dst), "l"(src))
#define CP_COMMIT() asm volatile("cp.async.commit_group;" ::: "memory")
#define CP_WAIT(n)  asm volatile("cp.async.wait_group %0;" :: "n"(n) : "memory")

__device__ __forceinline__ void ldm_x4(uint32_t* r, uint32_t addr) {
    asm volatile("ldmatrix.sync.aligned.m8n8.x4.shared.b16 {%0,%1,%2,%3}, [%4];"
        : "=r"(r[0]), "=r"(r[1]), "=r"(r[2]), "=r"(r[3]) : "r"(addr));
}

__device__ __forceinline__ void mma_bf16(float* d, const uint32_t* a,
                                         uint32_t b0, uint32_t b1) {
    asm volatile(
        "mma.sync.aligned.m16n8k16.row.col.f32.bf16.bf16.f32 "
        "{%0,%1,%2,%3}, {%4,%5,%6,%7}, {%8,%9}, {%0,%1,%2,%3};"
        : "+f"(d[0]), "+f"(d[1]), "+f"(d[2]), "+f"(d[3])
        : "r"(a[0]), "r"(a[1]), "r"(a[2]), "r"(a[3]), "r"(b0), "r"(b1));
}

// ---------------------------------------------------------------------------
// fp32 -> (bf16 hi, bf16 lo) split, vectorized
// ---------------------------------------------------------------------------
__global__ void split_bf16(const float* __restrict__ x,
                           __nv_bfloat16* __restrict__ hi,
                           __nv_bfloat16* __restrict__ lo, size_t n4)
{
    size_t i = (size_t)blockIdx.x * blockDim.x + threadIdx.x;
    if (i >= n4) return;
    float4 v = ((const float4*)x)[i];
    __nv_bfloat16 h0 = __float2bfloat16(v.x);
    __nv_bfloat16 h1 = __float2bfloat16(v.y);
    __nv_bfloat16 h2 = __float2bfloat16(v.z);
    __nv_bfloat16 h3 = __float2bfloat16(v.w);
    __nv_bfloat162 H0; H0.x = h0; H0.y = h1;
    __nv_bfloat162 H1; H1.x = h2; H1.y = h3;
    ((__nv_bfloat162*)hi)[2*i]   = H0;
    ((__nv_bfloat162*)hi)[2*i+1] = H1;
    __nv_bfloat162 L0, L1;
    L0.x = __float2bfloat16(v.x - __bfloat162float(h0));
    L0.y = __float2bfloat16(v.y - __bfloat162float(h1));
    L1.x = __float2bfloat16(v.z - __bfloat162float(h2));
    L1.y = __float2bfloat16(v.w - __bfloat162float(h3));
    ((__nv_bfloat162*)lo)[2*i]   = L0;
    ((__nv_bfloat162*)lo)[2*i+1] = L1;
}

// ---------------------------------------------------------------------------
// bf16x3 HMMA GEMM:  C[M,N] (fp32) = A[M,K] @ B[N,K]^T
//   C ≈ Ah·Bh + Ah·Bl + Al·Bh  (bf16 splits, fp32 register accumulate)
// CTA 128x128, 8 warps (4 M x 2 N), warp tile 32x64, K chunks of 32,
// 3-stage cp.async pipeline. Smem rows padded to 80B -> conflict-free ldmatrix.
// ---------------------------------------------------------------------------
#define BM 128
#define BN 128
#define BK 32
#define ROWB 80                      // bytes per smem row (32 bf16 + pad)
#define TILEB (128 * ROWB)           // 10240 bytes per logical tile
#define STAGEB (4 * TILEB)           // Ah, Al, Bh, Bl
#define NSTAGE 3
#define GEMM_SMEM_BYTES (NSTAGE * STAGEB)   // 122880

__global__ __launch_bounds__(256, 1)
void gemm_hmma(const __nv_bfloat16* __restrict__ Ah, const __nv_bfloat16* __restrict__ Al,
               const __nv_bfloat16* __restrict__ Bh, const __nv_bfloat16* __restrict__ Bl,
               float* __restrict__ C, int M, int N, int K)
{
    extern __shared__ char smem[];
    const uint32_t sbase = smem_u32(smem);
    const int tid  = threadIdx.x;
    const int wid  = tid >> 5;
    const int lane = tid & 31;
    const int wm = wid & 3;          // 0..3 -> M offset wm*32
    const int wn = wid >> 2;         // 0..1 -> N offset wn*64
    const int m0 = blockIdx.x * BM;
    const int n0 = blockIdx.y * BN;
    const int NCH = K / BK;

    // per-thread cp.async source/dest precompute pieces
    auto load_stage = [&](int s, int kc) {
        const int k0 = kc * BK;
#pragma unroll
        for (int j = 0; j < 8; j++) {
            int id   = tid + j * 256;        // 0..2047
            int tile = id >> 9;              // 0=Ah 1=Al 2=Bh 3=Bl
            int idx  = id & 511;
            int row  = idx >> 2;
            int c16  = idx & 3;
            const __nv_bfloat16* sb =
                (tile == 0) ? Ah : (tile == 1) ? Al : (tile == 2) ? Bh : Bl;
            int grow = ((tile < 2) ? m0 : n0) + row;
            const void* src = sb + (size_t)grow * K + k0 + c16 * 8;
            uint32_t dst = sbase + s * STAGEB + tile * TILEB + row * ROWB + c16 * 16;
            CP_ASYNC16(dst, src);
        }
        CP_COMMIT();
    };

    float acc[2][8][4];
#pragma unroll
    for (int mi = 0; mi < 2; mi++)
#pragma unroll
        for (int nj = 0; nj < 8; nj++)
#pragma unroll
            for (int q = 0; q < 4; q++) acc[mi][nj][q] = 0.f;

    load_stage(0, 0);
    load_stage(1, 1);

    const int lr = lane & 15;            // ldmatrix row within 16
    const int lc = (lane >> 4) * 16;     // byte offset of 8-col group

    for (int c = 0; c < NCH; c++) {
        CP_WAIT(1);
        __syncthreads();
        if (c + 2 < NCH) load_stage((c + 2) % NSTAGE, c + 2);

        const uint32_t st = sbase + (c % NSTAGE) * STAGEB;
        const uint32_t sAh = st;
        const uint32_t sAl = st + TILEB;
        const uint32_t sBh = st + 2 * TILEB;
        const uint32_t sBl = st + 3 * TILEB;

#pragma unroll
        for (int kk = 0; kk < 2; kk++) {          // two k16 blocks per chunk
            const uint32_t koff = kk * 32 + lc;   // byte offset in row
            uint32_t ah[2][4], al[2][4];
#pragma unroll
            for (int mi = 0; mi < 2; mi++) {
                uint32_t ra = (wm * 32 + mi * 16 + lr) * ROWB + koff;
                ldm_x4(ah[mi], sAh + ra);
                ldm_x4(al[mi], sAl + ra);
            }
            uint32_t bh[4][4], bl[4][4];
#pragma unroll
            for (int nj = 0; nj < 4; nj++) {
                uint32_t rb = (wn * 64 + nj * 16 + lr) * ROWB + koff;
                ldm_x4(bh[nj], sBh + rb);
                ldm_x4(bl[nj], sBl + rb);
            }
#pragma unroll
            for (int mi = 0; mi < 2; mi++) {
#pragma unroll
                for (int nj = 0; nj < 4; nj++) {
                    // n8 tile 2*nj   : b regs {r0, r2}
                    mma_bf16(acc[mi][2*nj],   ah[mi], bh[nj][0], bh[nj][2]);
                    mma_bf16(acc[mi][2*nj],   ah[mi], bl[nj][0], bl[nj][2]);
                    mma_bf16(acc[mi][2*nj],   al[mi], bh[nj][0], bh[nj][2]);
                    // n8 tile 2*nj+1 : b regs {r1, r3}
                    mma_bf16(acc[mi][2*nj+1], ah[mi], bh[nj][1], bh[nj][3]);
                    mma_bf16(acc[mi][2*nj+1], ah[mi], bl[nj][1], bl[nj][3]);
                    mma_bf16(acc[mi][2*nj+1], al[mi], bh[nj][1], bh[nj][3]);
                }
            }
        }
        __syncthreads();
    }

    // epilogue: mma d-fragment layout
    const int g  = lane >> 2;
    const int cc = (lane & 3) * 2;
#pragma unroll
    for (int mi = 0; mi < 2; mi++) {
        const int rbase = m0 + wm * 32 + mi * 16;
#pragma unroll
        for (int nj = 0; nj < 8; nj++) {
            const int cbase = n0 + wn * 64 + nj * 8 + cc;
            float2 v0 = make_float2(acc[mi][nj][0], acc[mi][nj][1]);
            float2 v1 = make_float2(acc[mi][nj][2], acc[mi][nj][3]);
            *(float2*)&C[(size_t)(rbase + g) * N + cbase]     = v0;
            *(float2*)&C[(size_t)(rbase + g + 8) * N + cbase] = v1;
        }
    }
}

// ---------------------------------------------------------------------------
// Flash-style attention, fp32 (unchanged — passes at 4e-6)
// ---------------------------------------------------------------------------
#define QT 64
#define KT 64
#define DSTR 132
#define PSTR 68
#define ATTN_SMEM_FLOATS (3*QT*DSTR + QT*PSTR)
#define ATTN_SMEM_BYTES  (ATTN_SMEM_FLOATS * 4)

__global__ __launch_bounds__(256)
void attn_kernel(const float* __restrict__ qkv, const float* __restrict__ mask,
                 float* __restrict__ out)
{
    const int qt = blockIdx.x;
    const int h  = blockIdx.y;
    const int b  = blockIdx.z;

    extern __shared__ float sm[];
    float* q_s = sm;
    float* k_s = q_s + QT * DSTR;
    float* v_s = k_s + QT * DSTR;
    float* p_s = v_s + QT * DSTR;

    const int tid = threadIdx.x;
    const int tx = tid & 15;
    const int ty = tid >> 4;
    const int q0 = qt * QT;

    const size_t qkv_stride = QKV_N;
    const float scale = 0.08838834764831845f;

#pragma unroll
    for (int i = 0; i < 8; i++) {
        int f = tid + i * 256;
        int row = f >> 5;
        int c4  = f & 31;
        const float* src = qkv + (size_t)(b*SEQ + q0 + row) * qkv_stride + h*HDIM + c4*4;
        *(float4*)&q_s[row*DSTR + c4*4] = *(const float4*)src;
    }

    float m[4], l[4], o[4][8];
#pragma unroll
    for (int r = 0; r < 4; r++) {
        m[r] = -INFINITY; l[r] = 0.f;
#pragma unroll
        for (int c = 0; c < 8; c++) o[r][c] = 0.f;
    }

    for (int kt = 0; kt <= qt; kt++) {
        const int k0 = kt * KT;
        __syncthreads();

#pragma unroll
        for (int i = 0; i < 8; i++) {
            int f = tid + i * 256;
            int row = f >> 5;
            int c4  = f & 31;
            const float* ksrc = qkv + (size_t)(b*SEQ + k0 + row) * qkv_stride + HID   + h*HDIM + c4*4;
            const float* vsrc = qkv + (size_t)(b*SEQ + k0 + row) * qkv_stride + 2*HID + h*HDIM + c4*4;
            *(float4*)&k_s[row*DSTR + c4*4] = *(const float4*)ksrc;
            *(float4*)&v_s[row*DSTR + c4*4] = *(const float4*)vsrc;
        }
        __syncthreads();

        float sacc[4][4];
#pragma unroll
        for (int r = 0; r < 4; r++)
#pragma unroll
            for (int c = 0; c < 4; c++) sacc[r][c] = 0.f;

        for (int d = 0; d < HDIM; d += 4) {
            float4 a[4], bb[4];
#pragma unroll
            for (int r = 0; r < 4; r++) a[r]  = *(const float4*)&q_s[(ty*4+r)*DSTR + d];
#pragma unroll
            for (int c = 0; c < 4; c++) bb[c] = *(const float4*)&k_s[(tx*4+c)*DSTR + d];
#pragma unroll
            for (int r = 0; r < 4; r++)
#pragma unroll
                for (int c = 0; c < 4; c++) {
                    sacc[r][c] = fmaf(a[r].x, bb[c].x, sacc[r][c]);
                    sacc[r][c] = fmaf(a[r].y, bb[c].y, sacc[r][c]);
                    sacc[r][c] = fmaf(a[r].z, bb[c].z, sacc[r][c]);
                    sacc[r][c] = fmaf(a[r].w, bb[c].w, sacc[r][c]);
                }
        }

#pragma unroll
        for (int r = 0; r < 4; r++) {
            const int qrow = q0 + ty*4 + r;
            const float* mrow = mask + ((size_t)h * SEQ + qrow) * SEQ + k0 + tx*4;
            float4 mk = *(const float4*)mrow;
            float s0 = sacc[r][0]*scale + mk.x;
            float s1 = sacc[r][1]*scale + mk.y;
            float s2 = sacc[r][2]*scale + mk.z;
            float s3 = sacc[r][3]*scale + mk.w;
            s0 = fmaxf(s0, -3.3e38f); s1 = fmaxf(s1, -3.3e38f);
            s2 = fmaxf(s2, -3.3e38f); s3 = fmaxf(s3, -3.3e38f);

            float rm = fmaxf(fmaxf(s0, s1), fmaxf(s2, s3));
#pragma unroll
            for (int off = 8; off >= 1; off >>= 1)
                rm = fmaxf(rm, __shfl_xor_sync(0xffffffffu, rm, off, 16));

            float mn = fmaxf(m[r], rm);
            float alpha = __expf(m[r] - mn);

            float p0 = __expf(s0 - mn);
            float p1 = __expf(s1 - mn);
            float p2 = __expf(s2 - mn);
            float p3 = __expf(s3 - mn);
            float* prow = &p_s[(ty*4+r)*PSTR + tx*4];
            prow[0] = p0; prow[1] = p1; prow[2] = p2; prow[3] = p3;

            float ps = p0 + p1 + p2 + p3;
#pragma unroll
            for (int off = 8; off >= 1; off >>= 1)
                ps += __shfl_xor_sync(0xffffffffu, ps, off, 16);

            l[r] = l[r] * alpha + ps;
            m[r] = mn;
#pragma unroll
            for (int c = 0; c < 8; c++) o[r][c] *= alpha;
        }
        __syncthreads();

        for (int j = 0; j < KT; j++) {
            float p0 = p_s[(ty*4+0)*PSTR + j];
            float p1 = p_s[(ty*4+1)*PSTR + j];
            float p2 = p_s[(ty*4+2)*PSTR + j];
            float p3 = p_s[(ty*4+3)*PSTR + j];
            float4 v0 = *(const float4*)&v_s[j*DSTR + tx*8];
            float4 v1 = *(const float4*)&v_s[j*DSTR + tx*8 + 4];
            o[0][0]=fmaf(p0,v0.x,o[0][0]); o[0][1]=fmaf(p0,v0.y,o[0][1]);
            o[0][2]=fmaf(p0,v0.z,o[0][2]); o[0][3]=fmaf(p0,v0.w,o[0][3]);
            o[0][4]=fmaf(p0,v1.x,o[0][4]); o[0][5]=fmaf(p0,v1.y,o[0][5]);
            o[0][6]=fmaf(p0,v1.z,o[0][6]); o[0][7]=fmaf(p0,v1.w,o[0][7]);
            o[1][0]=fmaf(p1,v0.x,o[1][0]); o[1][1]=fmaf(p1,v0.y,o[1][1]);
            o[1][2]=fmaf(p1,v0.z,o[1][2]); o[1][3]=fmaf(p1,v0.w,o[1][3]);
            o[1][4]=fmaf(p1,v1.x,o[1][4]); o[1][5]=fmaf(p1,v1.y,o[1][5]);
            o[1][6]=fmaf(p1,v1.z,o[1][6]); o[1][7]=fmaf(p1,v1.w,o[1][7]);
            o[2][0]=fmaf(p2,v0.x,o[2][0]); o[2][1]=fmaf(p2,v0.y,o[2][1]);
            o[2][2]=fmaf(p2,v0.z,o[2][2]); o[2][3]=fmaf(p2,v0.w,o[2][3]);
            o[2][4]=fmaf(p2,v1.x,o[2][4]); o[2][5]=fmaf(p2,v1.y,o[2][5]);
            o[2][6]=fmaf(p2,v1.z,o[2][6]); o[2][7]=fmaf(p2,v1.w,o[2][7]);
            o[3][0]=fmaf(p3,v0.x,o[3][0]); o[3][1]=fmaf(p3,v0.y,o[3][1]);
            o[3][2]=fmaf(p3,v0.z,o[3][2]); o[3][3]=fmaf(p3,v0.w,o[3][3]);
            o[3][4]=fmaf(p3,v1.x,o[3][4]); o[3][5]=fmaf(p3,v1.y,o[3][5]);
            o[3][6]=fmaf(p3,v1.z,o[3][6]); o[3][7]=fmaf(p3,v1.w,o[3][7]);
        }
    }

#pragma unroll
    for (int r = 0; r < 4; r++) {
        float inv = 1.0f / l[r];
        float* dst = out + (size_t)(b*SEQ + q0 + ty*4 + r) * HID + h*HDIM + tx*8;
        float4 w0 = make_float4(o[r][0]*inv, o[r][1]*inv, o[r][2]*inv, o[r][3]*inv);
        float4 w1 = make_float4(o[r][4]*inv, o[r][5]*inv, o[r][6]*inv, o[r][7]*inv);
        *(float4*)(dst)     = w0;
        *(float4*)(dst + 4) = w1;
    }
}

// ---------------------------------------------------------------------------
// Launch
// ---------------------------------------------------------------------------
extern "C" void kernel_launch(void* const* d_in, const int* in_sizes, int n_in,
                              void* d_out, int out_size)
{
    const float* hidden = (const float*)d_in[0];   // [2,1024,5120]
    const float* W_pack = (const float*)d_in[1];   // [15360,5120]
    const float* W_o    = (const float*)d_in[2];   // [5120,5120]
    const float* mask   = (const float*)d_in[3];   // [40,1024,1024]
    float* out = (float*)d_out;                    // [2,1024,5120]

    float *qkv, *attn;
    __nv_bfloat16 *hh, *hl, *ah, *al, *wph, *wpl, *woh, *wol;
    cudaGetSymbolAddress((void**)&qkv,  g_qkv);
    cudaGetSymbolAddress((void**)&attn, g_attn);
    cudaGetSymbolAddress((void**)&hh,  g_hh);
    cudaGetSymbolAddress((void**)&hl,  g_hl);
    cudaGetSymbolAddress((void**)&ah,  g_ah);
    cudaGetSymbolAddress((void**)&al,  g_al);
    cudaGetSymbolAddress((void**)&wph, g_wph);
    cudaGetSymbolAddress((void**)&wpl, g_wpl);
    cudaGetSymbolAddress((void**)&woh, g_woh);
    cudaGetSymbolAddress((void**)&wol, g_wol);

    cudaFuncSetAttribute(gemm_hmma, cudaFuncAttributeMaxDynamicSharedMemorySize,
                         GEMM_SMEM_BYTES);
    cudaFuncSetAttribute(attn_kernel, cudaFuncAttributeMaxDynamicSharedMemorySize,
                         ATTN_SMEM_BYTES);

    // bf16 hi/lo splits
    {
        size_t n4;
        n4 = (size_t)QKV_N * HID / 4;
        split_bf16<<<(unsigned)((n4 + 255) / 256), 256>>>(W_pack, wph, wpl, n4);
        n4 = (size_t)HID * HID / 4;
        split_bf16<<<(unsigned)((n4 + 255) / 256), 256>>>(W_o, woh, wol, n4);
        n4 = (size_t)MROWS * HID / 4;
        split_bf16<<<(unsigned)((n4 + 255) / 256), 256>>>(hidden, hh, hl, n4);
    }

    // GEMM1: qkv[2048,15360] = hidden @ W_pack^T
    gemm_hmma<<<dim3(MROWS/BM, QKV_N/BN), 256, GEMM_SMEM_BYTES>>>(
        hh, hl, wph, wpl, qkv, MROWS, QKV_N, HID);

    // Attention
    attn_kernel<<<dim3(SEQ/QT, NHEAD, BATCH), 256, ATTN_SMEM_BYTES>>>(qkv, mask, attn);

    // split attention output for GEMM2
    {
        size_t n4 = (size_t)MROWS * HID / 4;
        split_bf16<<<(unsigned)((n4 + 255) / 256), 256>>>(attn, ah, al, n4);
    }

    // GEMM2: out[2048,5120] = attn @ W_o^T
    gemm_hmma<<<dim3(MROWS/BM, HID/BN), 256, GEMM_SMEM_BYTES>>>(
        ah, al, woh, wol, out, MROWS, HID, HID);
}

// round 4
// speedup vs baseline: 2.0939x; 1.0911x over previous
#include <cuda_runtime.h>
#include <cuda_bf16.h>
#include <math.h>
#include <stdint.h>

// Problem constants
#define BATCH 2
#define SEQ   1024
#define HID   5120
#define NHEAD 40
#define HDIM  128
#define QKV_N (3*HID)          // 15360
#define MROWS (BATCH*SEQ)      // 2048

// ---------------------------------------------------------------------------
// Scratch
// ---------------------------------------------------------------------------
__device__ float g_qkv[(size_t)MROWS * QKV_N];   // [2048, 15360]
__device__ float g_attn[(size_t)MROWS * HID];    // [2048, 5120]
__device__ __nv_bfloat16 g_hh[(size_t)MROWS * HID];
__device__ __nv_bfloat16 g_hl[(size_t)MROWS * HID];
__device__ __nv_bfloat16 g_ah[(size_t)MROWS * HID];
__device__ __nv_bfloat16 g_al[(size_t)MROWS * HID];
__device__ __nv_bfloat16 g_wph[(size_t)QKV_N * HID];
__device__ __nv_bfloat16 g_wpl[(size_t)QKV_N * HID];
__device__ __nv_bfloat16 g_woh[(size_t)HID * HID];
__device__ __nv_bfloat16 g_wol[(size_t)HID * HID];

// ---------------------------------------------------------------------------
// PTX helpers (compute_103-safe: sm_80-era instructions only)
// ---------------------------------------------------------------------------
__device__ __forceinline__ uint32_t smem_u32(const void* p) {
    uint32_t a;
    asm("{ .reg .u64 t; cvta.to.shared.u64 t, %1; cvt.u32.u64 %0, t; }"
        : "=r"(a) : "l"(p));
    return a;
}

#define CP_ASYNC16(dst, src) \
    asm volatile("cp.async.cg.shared.global [%0], [%1], 16;" \
        :: "r"(dst), "l"(src))
#define CP_COMMIT() asm volatile("cp.async.commit_group;" ::: "memory")
#define CP_WAIT(n)  asm volatile("cp.async.wait_group %0;" :: "n"(n) : "memory")

__device__ __forceinline__ void ldm_x4(uint32_t* r, uint32_t addr) {
    asm volatile("ldmatrix.sync.aligned.m8n8.x4.shared.b16 {%0,%1,%2,%3}, [%4];"
        : "=r"(r[0]), "=r"(r[1]), "=r"(r[2]), "=r"(r[3]) : "r"(addr));
}

__device__ __forceinline__ void mma_bf16(float* d, const uint32_t* a,
                                         uint32_t b0, uint32_t b1) {
    asm volatile(
        "mma.sync.aligned.m16n8k16.row.col.f32.bf16.bf16.f32 "
        "{%0,%1,%2,%3}, {%4,%5,%6,%7}, {%8,%9}, {%0,%1,%2,%3};"
        : "+f"(d[0]), "+f"(d[1]), "+f"(d[2]), "+f"(d[3])
        : "r"(a[0]), "r"(a[1]), "r"(a[2]), "r"(a[3]), "r"(b0), "r"(b1));
}

// ---------------------------------------------------------------------------
// fp32 -> (bf16 hi, bf16 lo) split, vectorized
// ---------------------------------------------------------------------------
__global__ void split_bf16(const float* __restrict__ x,
                           __nv_bfloat16* __restrict__ hi,
                           __nv_bfloat16* __restrict__ lo, size_t n4)
{
    size_t i = (size_t)blockIdx.x * blockDim.x + threadIdx.x;
    if (i >= n4) return;
    float4 v = ((const float4*)x)[i];
    __nv_bfloat16 h0 = __float2bfloat16(v.x);
    __nv_bfloat16 h1 = __float2bfloat16(v.y);
    __nv_bfloat16 h2 = __float2bfloat16(v.z);
    __nv_bfloat16 h3 = __float2bfloat16(v.w);
    __nv_bfloat162 H0; H0.x = h0; H0.y = h1;
    __nv_bfloat162 H1; H1.x = h2; H1.y = h3;
    ((__nv_bfloat162*)hi)[2*i]   = H0;
    ((__nv_bfloat162*)hi)[2*i+1] = H1;
    __nv_bfloat162 L0, L1;
    L0.x = __float2bfloat16(v.x - __bfloat162float(h0));
    L0.y = __float2bfloat16(v.y - __bfloat162float(h1));
    L1.x = __float2bfloat16(v.z - __bfloat162float(h2));
    L1.y = __float2bfloat16(v.w - __bfloat162float(h3));
    ((__nv_bfloat162*)lo)[2*i]   = L0;
    ((__nv_bfloat162*)lo)[2*i+1] = L1;
}

// ---------------------------------------------------------------------------
// bf16x3 HMMA GEMM:  C[M,N] (fp32) = A[M,K] @ B[N,K]^T
//   C ≈ Ah·Bh + Ah·Bl + Al·Bh  (bf16 splits, fp32 register accumulate)
// CTA 128x128, 8 warps (4 M x 2 N), warp tile 32x64.
// K chunks of 64, 2-stage cp.async pipeline, fragment double-buffering.
// Smem rows: 64 bf16 = 128B data, padded to 144B -> conflict-free ldmatrix
// (8 rows at word-stride 36 hit bank offsets 0,4,8,...,28).
// ---------------------------------------------------------------------------
#define BM 128
#define BN 128
#define BK 64
#define ROWB 144                     // bytes per smem row (64 bf16 + 16B pad)
#define TILEB (128 * ROWB)           // 18432 bytes per logical tile
#define STAGEB (4 * TILEB)           // Ah, Al, Bh, Bl = 73728
#define NSTAGE 2
#define GEMM_SMEM_BYTES (NSTAGE * STAGEB)   // 147456

__global__ __launch_bounds__(256, 1)
void gemm_hmma(const __nv_bfloat16* __restrict__ Ah, const __nv_bfloat16* __restrict__ Al,
               const __nv_bfloat16* __restrict__ Bh, const __nv_bfloat16* __restrict__ Bl,
               float* __restrict__ C, int M, int N, int K)
{
    extern __shared__ char smem[];
    const uint32_t sbase = smem_u32(smem);
    const int tid  = threadIdx.x;
    const int wid  = tid >> 5;
    const int lane = tid & 31;
    const int wm = wid & 3;          // 0..3 -> M offset wm*32
    const int wn = wid >> 2;         // 0..1 -> N offset wn*64
    const int m0 = blockIdx.x * BM;
    const int n0 = blockIdx.y * BN;
    const int NCH = K / BK;

    // stage loader: 4096 16B chunks, 16 per thread
    auto load_stage = [&](int s, int kc) {
        const int k0 = kc * BK;
#pragma unroll
        for (int j = 0; j < 16; j++) {
            int id   = tid + j * 256;        // 0..4095
            int tile = id >> 10;             // 0=Ah 1=Al 2=Bh 3=Bl
            int idx  = id & 1023;
            int row  = idx >> 3;             // 0..127
            int c16  = idx & 7;              // 0..7 (8 x 16B per 128B row)
            const __nv_bfloat16* sb =
                (tile == 0) ? Ah : (tile == 1) ? Al : (tile == 2) ? Bh : Bl;
            int grow = ((tile < 2) ? m0 : n0) + row;
            const void* src = sb + (size_t)grow * K + k0 + c16 * 8;
            uint32_t dst = sbase + s * STAGEB + tile * TILEB + row * ROWB + c16 * 16;
            CP_ASYNC16(dst, src);
        }
        CP_COMMIT();
    };

    float acc[2][8][4];
#pragma unroll
    for (int mi = 0; mi < 2; mi++)
#pragma unroll
        for (int nj = 0; nj < 8; nj++)
#pragma unroll
            for (int q = 0; q < 4; q++) acc[mi][nj][q] = 0.f;

    load_stage(0, 0);
    if (NCH > 1) load_stage(1, 1);

    const int lr = lane & 15;            // ldmatrix row within 16
    const int lc = (lane >> 4) * 16;     // byte offset of 8-col group

    // fragment double buffers
    uint32_t ah[2][2][4], al[2][2][4], bh[2][4][4], bl[2][4][4];

    // per-warp smem row bases (k-independent parts)
    const uint32_t rowA = (wm * 32 + lr) * ROWB + lc;
    const uint32_t rowB = (wn * 64 + lr) * ROWB + lc;

    auto load_frags = [&](int pb, uint32_t st, int kk) {
        const uint32_t koff = kk * 32;
        const uint32_t sAh = st;
        const uint32_t sAl = st + TILEB;
        const uint32_t sBh = st + 2 * TILEB;
        const uint32_t sBl = st + 3 * TILEB;
#pragma unroll
        for (int mi = 0; mi < 2; mi++) {
            uint32_t ra = rowA + mi * 16 * ROWB + koff;
            ldm_x4(ah[pb][mi], sAh + ra);
            ldm_x4(al[pb][mi], sAl + ra);
        }
#pragma unroll
        for (int nj = 0; nj < 4; nj++) {
            uint32_t rb = rowB + nj * 16 * ROWB + koff;
            ldm_x4(bh[pb][nj], sBh + rb);
            ldm_x4(bl[pb][nj], sBl + rb);
        }
    };

    auto do_mma = [&](int pb) {
#pragma unroll
        for (int mi = 0; mi < 2; mi++) {
#pragma unroll
            for (int nj = 0; nj < 4; nj++) {
                mma_bf16(acc[mi][2*nj],   ah[pb][mi], bh[pb][nj][0], bh[pb][nj][2]);
                mma_bf16(acc[mi][2*nj],   ah[pb][mi], bl[pb][nj][0], bl[pb][nj][2]);
                mma_bf16(acc[mi][2*nj],   al[pb][mi], bh[pb][nj][0], bh[pb][nj][2]);
                mma_bf16(acc[mi][2*nj+1], ah[pb][mi], bh[pb][nj][1], bh[pb][nj][3]);
                mma_bf16(acc[mi][2*nj+1], ah[pb][mi], bl[pb][nj][1], bl[pb][nj][3]);
                mma_bf16(acc[mi][2*nj+1], al[pb][mi], bh[pb][nj][1], bh[pb][nj][3]);
            }
        }
    };

    for (int c = 0; c < NCH; c++) {
        CP_WAIT(1);
        __syncthreads();

        const uint32_t st = sbase + (c & 1) * STAGEB;

        // 4 k16 blocks per chunk, fragments double-buffered
        load_frags(0, st, 0);
#pragma unroll
        for (int kk = 0; kk < 4; kk++) {
            if (kk < 3) load_frags((kk + 1) & 1, st, kk + 1);
            do_mma(kk & 1);
        }

        __syncthreads();
        if (c + 2 < NCH) load_stage(c & 1, c + 2);
    }

    // epilogue: mma d-fragment layout
    const int g  = lane >> 2;
    const int cc = (lane & 3) * 2;
#pragma unroll
    for (int mi = 0; mi < 2; mi++) {
        const int rbase = m0 + wm * 32 + mi * 16;
#pragma unroll
        for (int nj = 0; nj < 8; nj++) {
            const int cbase = n0 + wn * 64 + nj * 8 + cc;
            float2 v0 = make_float2(acc[mi][nj][0], acc[mi][nj][1]);
            float2 v1 = make_float2(acc[mi][nj][2], acc[mi][nj][3]);
            *(float2*)&C[(size_t)(rbase + g) * N + cbase]     = v0;
            *(float2*)&C[(size_t)(rbase + g + 8) * N + cbase] = v1;
        }
    }
}

// ---------------------------------------------------------------------------
// Flash-style attention, fp32 (unchanged — passes at 4e-6)
// ---------------------------------------------------------------------------
#define QT 64
#define KT 64
#define DSTR 132
#define PSTR 68
#define ATTN_SMEM_FLOATS (3*QT*DSTR + QT*PSTR)
#define ATTN_SMEM_BYTES  (ATTN_SMEM_FLOATS * 4)

__global__ __launch_bounds__(256)
void attn_kernel(const float* __restrict__ qkv, const float* __restrict__ mask,
                 float* __restrict__ out)
{
    const int qt = blockIdx.x;
    const int h  = blockIdx.y;
    const int b  = blockIdx.z;

    extern __shared__ float sm[];
    float* q_s = sm;
    float* k_s = q_s + QT * DSTR;
    float* v_s = k_s + QT * DSTR;
    float* p_s = v_s + QT * DSTR;

    const int tid = threadIdx.x;
    const int tx = tid & 15;
    const int ty = tid >> 4;
    const int q0 = qt * QT;

    const size_t qkv_stride = QKV_N;
    const float scale = 0.08838834764831845f;

#pragma unroll
    for (int i = 0; i < 8; i++) {
        int f = tid + i * 256;
        int row = f >> 5;
        int c4  = f & 31;
        const float* src = qkv + (size_t)(b*SEQ + q0 + row) * qkv_stride + h*HDIM + c4*4;
        *(float4*)&q_s[row*DSTR + c4*4] = *(const float4*)src;
    }

    float m[4], l[4], o[4][8];
#pragma unroll
    for (int r = 0; r < 4; r++) {
        m[r] = -INFINITY; l[r] = 0.f;
#pragma unroll
        for (int c = 0; c < 8; c++) o[r][c] = 0.f;
    }

    for (int kt = 0; kt <= qt; kt++) {
        const int k0 = kt * KT;
        __syncthreads();

#pragma unroll
        for (int i = 0; i < 8; i++) {
            int f = tid + i * 256;
            int row = f >> 5;
            int c4  = f & 31;
            const float* ksrc = qkv + (size_t)(b*SEQ + k0 + row) * qkv_stride + HID   + h*HDIM + c4*4;
            const float* vsrc = qkv + (size_t)(b*SEQ + k0 + row) * qkv_stride + 2*HID + h*HDIM + c4*4;
            *(float4*)&k_s[row*DSTR + c4*4] = *(const float4*)ksrc;
            *(float4*)&v_s[row*DSTR + c4*4] = *(const float4*)vsrc;
        }
        __syncthreads();

        float sacc[4][4];
#pragma unroll
        for (int r = 0; r < 4; r++)
#pragma unroll
            for (int c = 0; c < 4; c++) sacc[r][c] = 0.f;

        for (int d = 0; d < HDIM; d += 4) {
            float4 a[4], bb[4];
#pragma unroll
            for (int r = 0; r < 4; r++) a[r]  = *(const float4*)&q_s[(ty*4+r)*DSTR + d];
#pragma unroll
            for (int c = 0; c < 4; c++) bb[c] = *(const float4*)&k_s[(tx*4+c)*DSTR + d];
#pragma unroll
            for (int r = 0; r < 4; r++)
#pragma unroll
                for (int c = 0; c < 4; c++) {
                    sacc[r][c] = fmaf(a[r].x, bb[c].x, sacc[r][c]);
                    sacc[r][c] = fmaf(a[r].y, bb[c].y, sacc[r][c]);
                    sacc[r][c] = fmaf(a[r].z, bb[c].z, sacc[r][c]);
                    sacc[r][c] = fmaf(a[r].w, bb[c].w, sacc[r][c]);
                }
        }

#pragma unroll
        for (int r = 0; r < 4; r++) {
            const int qrow = q0 + ty*4 + r;
            const float* mrow = mask + ((size_t)h * SEQ + qrow) * SEQ + k0 + tx*4;
            float4 mk = *(const float4*)mrow;
            float s0 = sacc[r][0]*scale + mk.x;
            float s1 = sacc[r][1]*scale + mk.y;
            float s2 = sacc[r][2]*scale + mk.z;
            float s3 = sacc[r][3]*scale + mk.w;
            s0 = fmaxf(s0, -3.3e38f); s1 = fmaxf(s1, -3.3e38f);
            s2 = fmaxf(s2, -3.3e38f); s3 = fmaxf(s3, -3.3e38f);

            float rm = fmaxf(fmaxf(s0, s1), fmaxf(s2, s3));
#pragma unroll
            for (int off = 8; off >= 1; off >>= 1)
                rm = fmaxf(rm, __shfl_xor_sync(0xffffffffu, rm, off, 16));

            float mn = fmaxf(m[r], rm);
            float alpha = __expf(m[r] - mn);

            float p0 = __expf(s0 - mn);
            float p1 = __expf(s1 - mn);
            float p2 = __expf(s2 - mn);
            float p3 = __expf(s3 - mn);
            float* prow = &p_s[(ty*4+r)*PSTR + tx*4];
            prow[0] = p0; prow[1] = p1; prow[2] = p2; prow[3] = p3;

            float ps = p0 + p1 + p2 + p3;
#pragma unroll
            for (int off = 8; off >= 1; off >>= 1)
                ps += __shfl_xor_sync(0xffffffffu, ps, off, 16);

            l[r] = l[r] * alpha + ps;
            m[r] = mn;
#pragma unroll
            for (int c = 0; c < 8; c++) o[r][c] *= alpha;
        }
        __syncthreads();

        for (int j = 0; j < KT; j++) {
            float p0 = p_s[(ty*4+0)*PSTR + j];
            float p1 = p_s[(ty*4+1)*PSTR + j];
            float p2 = p_s[(ty*4+2)*PSTR + j];
            float p3 = p_s[(ty*4+3)*PSTR + j];
            float4 v0 = *(const float4*)&v_s[j*DSTR + tx*8];
            float4 v1 = *(const float4*)&v_s[j*DSTR + tx*8 + 4];
            o[0][0]=fmaf(p0,v0.x,o[0][0]); o[0][1]=fmaf(p0,v0.y,o[0][1]);
            o[0][2]=fmaf(p0,v0.z,o[0][2]); o[0][3]=fmaf(p0,v0.w,o[0][3]);
            o[0][4]=fmaf(p0,v1.x,o[0][4]); o[0][5]=fmaf(p0,v1.y,o[0][5]);
            o[0][6]=fmaf(p0,v1.z,o[0][6]); o[0][7]=fmaf(p0,v1.w,o[0][7]);
            o[1][0]=fmaf(p1,v0.x,o[1][0]); o[1][1]=fmaf(p1,v0.y,o[1][1]);
            o[1][2]=fmaf(p1,v0.z,o[1][2]); o[1][3]=fmaf(p1,v0.w,o[1][3]);
            o[1][4]=fmaf(p1,v1.x,o[1][4]); o[1][5]=fmaf(p1,v1.y,o[1][5]);
            o[1][6]=fmaf(p1,v1.z,o[1][6]); o[1][7]=fmaf(p1,v1.w,o[1][7]);
            o[2][0]=fmaf(p2,v0.x,o[2][0]); o[2][1]=fmaf(p2,v0.y,o[2][1]);
            o[2][2]=fmaf(p2,v0.z,o[2][2]); o[2][3]=fmaf(p2,v0.w,o[2][3]);
            o[2][4]=fmaf(p2,v1.x,o[2][4]); o[2][5]=fmaf(p2,v1.y,o[2][5]);
            o[2][6]=fmaf(p2,v1.z,o[2][6]); o[2][7]=fmaf(p2,v1.w,o[2][7]);
            o[3][0]=fmaf(p3,v0.x,o[3][0]); o[3][1]=fmaf(p3,v0.y,o[3][1]);
            o[3][2]=fmaf(p3,v0.z,o[3][2]); o[3][3]=fmaf(p3,v0.w,o[3][3]);
            o[3][4]=fmaf(p3,v1.x,o[3][4]); o[3][5]=fmaf(p3,v1.y,o[3][5]);
            o[3][6]=fmaf(p3,v1.z,o[3][6]); o[3][7]=fmaf(p3,v1.w,o[3][7]);
        }
    }

#pragma unroll
    for (int r = 0; r < 4; r++) {
        float inv = 1.0f / l[r];
        float* dst = out + (size_t)(b*SEQ + q0 + ty*4 + r) * HID + h*HDIM + tx*8;
        float4 w0 = make_float4(o[r][0]*inv, o[r][1]*inv, o[r][2]*inv, o[r][3]*inv);
        float4 w1 = make_float4(o[r][4]*inv, o[r][5]*inv, o[r][6]*inv, o[r][7]*inv);
        *(float4*)(dst)     = w0;
        *(float4*)(dst + 4) = w1;
    }
}

// ---------------------------------------------------------------------------
// Launch
// ---------------------------------------------------------------------------
extern "C" void kernel_launch(void* const* d_in, const int* in_sizes, int n_in,
                              void* d_out, int out_size)
{
    const float* hidden = (const float*)d_in[0];   // [2,1024,5120]
    const float* W_pack = (const float*)d_in[1];   // [15360,5120]
    const float* W_o    = (const float*)d_in[2];   // [5120,5120]
    const float* mask   = (const float*)d_in[3];   // [40,1024,1024]
    float* out = (float*)d_out;                    // [2,1024,5120]

    float *qkv, *attn;
    __nv_bfloat16 *hh, *hl, *ah, *al, *wph, *wpl, *woh, *wol;
    cudaGetSymbolAddress((void**)&qkv,  g_qkv);
    cudaGetSymbolAddress((void**)&attn, g_attn);
    cudaGetSymbolAddress((void**)&hh,  g_hh);
    cudaGetSymbolAddress((void**)&hl,  g_hl);
    cudaGetSymbolAddress((void**)&ah,  g_ah);
    cudaGetSymbolAddress((void**)&al,  g_al);
    cudaGetSymbolAddress((void**)&wph, g_wph);
    cudaGetSymbolAddress((void**)&wpl, g_wpl);
    cudaGetSymbolAddress((void**)&woh, g_woh);
    cudaGetSymbolAddress((void**)&wol, g_wol);

    cudaFuncSetAttribute(gemm_hmma, cudaFuncAttributeMaxDynamicSharedMemorySize,
                         GEMM_SMEM_BYTES);
    cudaFuncSetAttribute(attn_kernel, cudaFuncAttributeMaxDynamicSharedMemorySize,
                         ATTN_SMEM_BYTES);

    // bf16 hi/lo splits
    {
        size_t n4;
        n4 = (size_t)QKV_N * HID / 4;
        split_bf16<<<(unsigned)((n4 + 255) / 256), 256>>>(W_pack, wph, wpl, n4);
        n4 = (size_t)HID * HID / 4;
        split_bf16<<<(unsigned)((n4 + 255) / 256), 256>>>(W_o, woh, wol, n4);
        n4 = (size_t)MROWS * HID / 4;
        split_bf16<<<(unsigned)((n4 + 255) / 256), 256>>>(hidden, hh, hl, n4);
    }

    // GEMM1: qkv[2048,15360] = hidden @ W_pack^T
    gemm_hmma<<<dim3(MROWS/BM, QKV_N/BN), 256, GEMM_SMEM_BYTES>>>(
        hh, hl, wph, wpl, qkv, MROWS, QKV_N, HID);

    // Attention
    attn_kernel<<<dim3(SEQ/QT, NHEAD, BATCH), 256, ATTN_SMEM_BYTES>>>(qkv, mask, attn);

    // split attention output for GEMM2
    {
        size_t n4 = (size_t)MROWS * HID / 4;
        split_bf16<<<(unsigned)((n4 + 255) / 256), 256>>>(attn, ah, al, n4);
    }

    // GEMM2: out[2048,5120] = attn @ W_o^T
    gemm_hmma<<<dim3(MROWS/BM, HID/BN), 256, GEMM_SMEM_BYTES>>>(
        ah, al, woh, wol, out, MROWS, HID, HID);
}

// round 5
// speedup vs baseline: 2.0977x; 1.0018x over previous
#include <cuda_runtime.h>
#include <cuda_bf16.h>
#include <math.h>
#include <stdint.h>

// Problem constants
#define BATCH 2
#define SEQ   1024
#define HID   5120
#define NHEAD 40
#define HDIM  128
#define QKV_N (3*HID)          // 15360
#define MROWS (BATCH*SEQ)      // 2048

// ---------------------------------------------------------------------------
// Scratch
// ---------------------------------------------------------------------------
__device__ float g_qkv[(size_t)MROWS * QKV_N];   // [2048, 15360]
__device__ float g_attn[(size_t)MROWS * HID];    // [2048, 5120]
__device__ __nv_bfloat16 g_hh[(size_t)MROWS * HID];
__device__ __nv_bfloat16 g_hl[(size_t)MROWS * HID];
__device__ __nv_bfloat16 g_ah[(size_t)MROWS * HID];
__device__ __nv_bfloat16 g_al[(size_t)MROWS * HID];
__device__ __nv_bfloat16 g_wph[(size_t)QKV_N * HID];
__device__ __nv_bfloat16 g_wpl[(size_t)QKV_N * HID];
__device__ __nv_bfloat16 g_woh[(size_t)HID * HID];
__device__ __nv_bfloat16 g_wol[(size_t)HID * HID];

// ---------------------------------------------------------------------------
// PTX helpers (compute_103-safe: sm_80-era instructions only)
// ---------------------------------------------------------------------------
__device__ __forceinline__ uint32_t smem_u32(const void* p) {
    uint32_t a;
    asm("{ .reg .u64 t; cvta.to.shared.u64 t, %1; cvt.u32.u64 %0, t; }"
        : "=r"(a) : "l"(p));
    return a;
}

#define CP_ASYNC16(dst, src) \
    asm volatile("cp.async.cg.shared.global [%0], [%1], 16;" \
        :: "r"(dst), "l"(src))
#define CP_COMMIT() asm volatile("cp.async.commit_group;" ::: "memory")
#define CP_WAIT(n)  asm volatile("cp.async.wait_group %0;" :: "n"(n) : "memory")

__device__ __forceinline__ void ldm_x4(uint32_t* r, uint32_t addr) {
    asm volatile("ldmatrix.sync.aligned.m8n8.x4.shared.b16 {%0,%1,%2,%3}, [%4];"
        : "=r"(r[0]), "=r"(r[1]), "=r"(r[2]), "=r"(r[3]) : "r"(addr));
}

__device__ __forceinline__ void mma_bf16(float* d, const uint32_t* a,
                                         uint32_t b0, uint32_t b1) {
    asm volatile(
        "mma.sync.aligned.m16n8k16.row.col.f32.bf16.bf16.f32 "
        "{%0,%1,%2,%3}, {%4,%5,%6,%7}, {%8,%9}, {%0,%1,%2,%3};"
        : "+f"(d[0]), "+f"(d[1]), "+f"(d[2]), "+f"(d[3])
        : "r"(a[0]), "r"(a[1]), "r"(a[2]), "r"(a[3]), "r"(b0), "r"(b1));
}

// ---------------------------------------------------------------------------
// fp32 -> (bf16 hi, bf16 lo) split, vectorized
// ---------------------------------------------------------------------------
__global__ void split_bf16(const float* __restrict__ x,
                           __nv_bfloat16* __restrict__ hi,
                           __nv_bfloat16* __restrict__ lo, size_t n4)
{
    size_t i = (size_t)blockIdx.x * blockDim.x + threadIdx.x;
    if (i >= n4) return;
    float4 v = ((const float4*)x)[i];
    __nv_bfloat16 h0 = __float2bfloat16(v.x);
    __nv_bfloat16 h1 = __float2bfloat16(v.y);
    __nv_bfloat16 h2 = __float2bfloat16(v.z);
    __nv_bfloat16 h3 = __float2bfloat16(v.w);
    __nv_bfloat162 H0; H0.x = h0; H0.y = h1;
    __nv_bfloat162 H1; H1.x = h2; H1.y = h3;
    ((__nv_bfloat162*)hi)[2*i]   = H0;
    ((__nv_bfloat162*)hi)[2*i+1] = H1;
    __nv_bfloat162 L0, L1;
    L0.x = __float2bfloat16(v.x - __bfloat162float(h0));
    L0.y = __float2bfloat16(v.y - __bfloat162float(h1));
    L1.x = __float2bfloat16(v.z - __bfloat162float(h2));
    L1.y = __float2bfloat16(v.w - __bfloat162float(h3));
    ((__nv_bfloat162*)lo)[2*i]   = L0;
    ((__nv_bfloat162*)lo)[2*i+1] = L1;
}

// ---------------------------------------------------------------------------
// bf16x3 HMMA GEMM:  C[M,N] (fp32) = A[M,K] @ B[N,K]^T
//   C ≈ Ah·Bh + Ah·Bl + Al·Bh  (bf16 splits, fp32 register accumulate)
// CTA 128x128, 16 warps (4 M x 4 N), warp tile 32x32 -> 4 warps/SMSP.
// K chunks of 64, 2-stage cp.async pipeline.
// Smem rows: 64 bf16 = 128B data, padded to 144B -> conflict-free ldmatrix.
// ---------------------------------------------------------------------------
#define BM 128
#define BN 128
#define BK 64
#define ROWB 144                     // bytes per smem row (64 bf16 + 16B pad)
#define TILEB (128 * ROWB)           // 18432 bytes per logical tile
#define STAGEB (4 * TILEB)           // Ah, Al, Bh, Bl = 73728
#define NSTAGE 2
#define GEMM_SMEM_BYTES (NSTAGE * STAGEB)   // 147456
#define GTHREADS 512

__global__ __launch_bounds__(GTHREADS, 1)
void gemm_hmma(const __nv_bfloat16* __restrict__ Ah, const __nv_bfloat16* __restrict__ Al,
               const __nv_bfloat16* __restrict__ Bh, const __nv_bfloat16* __restrict__ Bl,
               float* __restrict__ C, int M, int N, int K)
{
    extern __shared__ char smem[];
    const uint32_t sbase = smem_u32(smem);
    const int tid  = threadIdx.x;
    const int wid  = tid >> 5;
    const int lane = tid & 31;
    const int wm = wid & 3;          // 0..3 -> M offset wm*32
    const int wn = wid >> 2;         // 0..3 -> N offset wn*32
    const int m0 = blockIdx.x * BM;
    const int n0 = blockIdx.y * BN;
    const int NCH = K / BK;

    // stage loader: 4096 16B chunks, 8 per thread
    auto load_stage = [&](int s, int kc) {
        const int k0 = kc * BK;
#pragma unroll
        for (int j = 0; j < 8; j++) {
            int id   = tid + j * GTHREADS;   // 0..4095
            int tile = id >> 10;             // 0=Ah 1=Al 2=Bh 3=Bl
            int idx  = id & 1023;
            int row  = idx >> 3;             // 0..127
            int c16  = idx & 7;              // 0..7 (8 x 16B per 128B row)
            const __nv_bfloat16* sb =
                (tile == 0) ? Ah : (tile == 1) ? Al : (tile == 2) ? Bh : Bl;
            int grow = ((tile < 2) ? m0 : n0) + row;
            const void* src = sb + (size_t)grow * K + k0 + c16 * 8;
            uint32_t dst = sbase + s * STAGEB + tile * TILEB + row * ROWB + c16 * 16;
            CP_ASYNC16(dst, src);
        }
        CP_COMMIT();
    };

    float acc[2][4][4];
#pragma unroll
    for (int mi = 0; mi < 2; mi++)
#pragma unroll
        for (int nj = 0; nj < 4; nj++)
#pragma unroll
            for (int q = 0; q < 4; q++) acc[mi][nj][q] = 0.f;

    load_stage(0, 0);
    if (NCH > 1) load_stage(1, 1);

    const int lr = lane & 15;            // ldmatrix row within 16
    const int lc = (lane >> 4) * 16;     // byte offset of 8-col group

    // per-warp smem row bases (k-independent parts)
    const uint32_t rowA = (wm * 32 + lr) * ROWB + lc;
    const uint32_t rowB = (wn * 32 + lr) * ROWB + lc;

    for (int c = 0; c < NCH; c++) {
        CP_WAIT(1);
        __syncthreads();

        const uint32_t st  = sbase + (c & 1) * STAGEB;
        const uint32_t sAh = st;
        const uint32_t sAl = st + TILEB;
        const uint32_t sBh = st + 2 * TILEB;
        const uint32_t sBl = st + 3 * TILEB;

#pragma unroll
        for (int kk = 0; kk < 4; kk++) {
            const uint32_t koff = kk * 32;
            uint32_t ahf[2][4], alf[2][4], bhf[2][4], blf[2][4];
#pragma unroll
            for (int mi = 0; mi < 2; mi++) {
                uint32_t ra = rowA + mi * 16 * ROWB + koff;
                ldm_x4(ahf[mi], sAh + ra);
                ldm_x4(alf[mi], sAl + ra);
            }
#pragma unroll
            for (int nj = 0; nj < 2; nj++) {
                uint32_t rb = rowB + nj * 16 * ROWB + koff;
                ldm_x4(bhf[nj], sBh + rb);
                ldm_x4(blf[nj], sBl + rb);
            }
#pragma unroll
            for (int mi = 0; mi < 2; mi++) {
#pragma unroll
                for (int nj = 0; nj < 2; nj++) {
                    mma_bf16(acc[mi][2*nj],   ahf[mi], bhf[nj][0], bhf[nj][2]);
                    mma_bf16(acc[mi][2*nj],   ahf[mi], blf[nj][0], blf[nj][2]);
                    mma_bf16(acc[mi][2*nj],   alf[mi], bhf[nj][0], bhf[nj][2]);
                    mma_bf16(acc[mi][2*nj+1], ahf[mi], bhf[nj][1], bhf[nj][3]);
                    mma_bf16(acc[mi][2*nj+1], ahf[mi], blf[nj][1], blf[nj][3]);
                    mma_bf16(acc[mi][2*nj+1], alf[mi], bhf[nj][1], bhf[nj][3]);
                }
            }
        }

        __syncthreads();
        if (c + 2 < NCH) load_stage(c & 1, c + 2);
    }

    // epilogue: mma d-fragment layout
    const int g  = lane >> 2;
    const int cc = (lane & 3) * 2;
#pragma unroll
    for (int mi = 0; mi < 2; mi++) {
        const int rbase = m0 + wm * 32 + mi * 16;
#pragma unroll
        for (int nj = 0; nj < 4; nj++) {
            const int cbase = n0 + wn * 32 + nj * 8 + cc;
            float2 v0 = make_float2(acc[mi][nj][0], acc[mi][nj][1]);
            float2 v1 = make_float2(acc[mi][nj][2], acc[mi][nj][3]);
            *(float2*)&C[(size_t)(rbase + g) * N + cbase]     = v0;
            *(float2*)&C[(size_t)(rbase + g + 8) * N + cbase] = v1;
        }
    }
}

// ---------------------------------------------------------------------------
// Flash-style attention, fp32 (unchanged — passes at 4e-6)
// ---------------------------------------------------------------------------
#define QT 64
#define KT 64
#define DSTR 132
#define PSTR 68
#define ATTN_SMEM_FLOATS (3*QT*DSTR + QT*PSTR)
#define ATTN_SMEM_BYTES  (ATTN_SMEM_FLOATS * 4)

__global__ __launch_bounds__(256)
void attn_kernel(const float* __restrict__ qkv, const float* __restrict__ mask,
                 float* __restrict__ out)
{
    const int qt = blockIdx.x;
    const int h  = blockIdx.y;
    const int b  = blockIdx.z;

    extern __shared__ float sm[];
    float* q_s = sm;
    float* k_s = q_s + QT * DSTR;
    float* v_s = k_s + QT * DSTR;
    float* p_s = v_s + QT * DSTR;

    const int tid = threadIdx.x;
    const int tx = tid & 15;
    const int ty = tid >> 4;
    const int q0 = qt * QT;

    const size_t qkv_stride = QKV_N;
    const float scale = 0.08838834764831845f;

#pragma unroll
    for (int i = 0; i < 8; i++) {
        int f = tid + i * 256;
        int row = f >> 5;
        int c4  = f & 31;
        const float* src = qkv + (size_t)(b*SEQ + q0 + row) * qkv_stride + h*HDIM + c4*4;
        *(float4*)&q_s[row*DSTR + c4*4] = *(const float4*)src;
    }

    float m[4], l[4], o[4][8];
#pragma unroll
    for (int r = 0; r < 4; r++) {
        m[r] = -INFINITY; l[r] = 0.f;
#pragma unroll
        for (int c = 0; c < 8; c++) o[r][c] = 0.f;
    }

    for (int kt = 0; kt <= qt; kt++) {
        const int k0 = kt * KT;
        __syncthreads();

#pragma unroll
        for (int i = 0; i < 8; i++) {
            int f = tid + i * 256;
            int row = f >> 5;
            int c4  = f & 31;
            const float* ksrc = qkv + (size_t)(b*SEQ + k0 + row) * qkv_stride + HID   + h*HDIM + c4*4;
            const float* vsrc = qkv + (size_t)(b*SEQ + k0 + row) * qkv_stride + 2*HID + h*HDIM + c4*4;
            *(float4*)&k_s[row*DSTR + c4*4] = *(const float4*)ksrc;
            *(float4*)&v_s[row*DSTR + c4*4] = *(const float4*)vsrc;
        }
        __syncthreads();

        float sacc[4][4];
#pragma unroll
        for (int r = 0; r < 4; r++)
#pragma unroll
            for (int c = 0; c < 4; c++) sacc[r][c] = 0.f;

        for (int d = 0; d < HDIM; d += 4) {
            float4 a[4], bb[4];
#pragma unroll
            for (int r = 0; r < 4; r++) a[r]  = *(const float4*)&q_s[(ty*4+r)*DSTR + d];
#pragma unroll
            for (int c = 0; c < 4; c++) bb[c] = *(const float4*)&k_s[(tx*4+c)*DSTR + d];
#pragma unroll
            for (int r = 0; r < 4; r++)
#pragma unroll
                for (int c = 0; c < 4; c++) {
                    sacc[r][c] = fmaf(a[r].x, bb[c].x, sacc[r][c]);
                    sacc[r][c] = fmaf(a[r].y, bb[c].y, sacc[r][c]);
                    sacc[r][c] = fmaf(a[r].z, bb[c].z, sacc[r][c]);
                    sacc[r][c] = fmaf(a[r].w, bb[c].w, sacc[r][c]);
                }
        }

#pragma unroll
        for (int r = 0; r < 4; r++) {
            const int qrow = q0 + ty*4 + r;
            const float* mrow = mask + ((size_t)h * SEQ + qrow) * SEQ + k0 + tx*4;
            float4 mk = *(const float4*)mrow;
            float s0 = sacc[r][0]*scale + mk.x;
            float s1 = sacc[r][1]*scale + mk.y;
            float s2 = sacc[r][2]*scale + mk.z;
            float s3 = sacc[r][3]*scale + mk.w;
            s0 = fmaxf(s0, -3.3e38f); s1 = fmaxf(s1, -3.3e38f);
            s2 = fmaxf(s2, -3.3e38f); s3 = fmaxf(s3, -3.3e38f);

            float rm = fmaxf(fmaxf(s0, s1), fmaxf(s2, s3));
#pragma unroll
            for (int off = 8; off >= 1; off >>= 1)
                rm = fmaxf(rm, __shfl_xor_sync(0xffffffffu, rm, off, 16));

            float mn = fmaxf(m[r], rm);
            float alpha = __expf(m[r] - mn);

            float p0 = __expf(s0 - mn);
            float p1 = __expf(s1 - mn);
            float p2 = __expf(s2 - mn);
            float p3 = __expf(s3 - mn);
            float* prow = &p_s[(ty*4+r)*PSTR + tx*4];
            prow[0] = p0; prow[1] = p1; prow[2] = p2; prow[3] = p3;

            float ps = p0 + p1 + p2 + p3;
#pragma unroll
            for (int off = 8; off >= 1; off >>= 1)
                ps += __shfl_xor_sync(0xffffffffu, ps, off, 16);

            l[r] = l[r] * alpha + ps;
            m[r] = mn;
#pragma unroll
            for (int c = 0; c < 8; c++) o[r][c] *= alpha;
        }
        __syncthreads();

        for (int j = 0; j < KT; j++) {
            float p0 = p_s[(ty*4+0)*PSTR + j];
            float p1 = p_s[(ty*4+1)*PSTR + j];
            float p2 = p_s[(ty*4+2)*PSTR + j];
            float p3 = p_s[(ty*4+3)*PSTR + j];
            float4 v0 = *(const float4*)&v_s[j*DSTR + tx*8];
            float4 v1 = *(const float4*)&v_s[j*DSTR + tx*8 + 4];
            o[0][0]=fmaf(p0,v0.x,o[0][0]); o[0][1]=fmaf(p0,v0.y,o[0][1]);
            o[0][2]=fmaf(p0,v0.z,o[0][2]); o[0][3]=fmaf(p0,v0.w,o[0][3]);
            o[0][4]=fmaf(p0,v1.x,o[0][4]); o[0][5]=fmaf(p0,v1.y,o[0][5]);
            o[0][6]=fmaf(p0,v1.z,o[0][6]); o[0][7]=fmaf(p0,v1.w,o[0][7]);
            o[1][0]=fmaf(p1,v0.x,o[1][0]); o[1][1]=fmaf(p1,v0.y,o[1][1]);
            o[1][2]=fmaf(p1,v0.z,o[1][2]); o[1][3]=fmaf(p1,v0.w,o[1][3]);
            o[1][4]=fmaf(p1,v1.x,o[1][4]); o[1][5]=fmaf(p1,v1.y,o[1][5]);
            o[1][6]=fmaf(p1,v1.z,o[1][6]); o[1][7]=fmaf(p1,v1.w,o[1][7]);
            o[2][0]=fmaf(p2,v0.x,o[2][0]); o[2][1]=fmaf(p2,v0.y,o[2][1]);
            o[2][2]=fmaf(p2,v0.z,o[2][2]); o[2][3]=fmaf(p2,v0.w,o[2][3]);
            o[2][4]=fmaf(p2,v1.x,o[2][4]); o[2][5]=fmaf(p2,v1.y,o[2][5]);
            o[2][6]=fmaf(p2,v1.z,o[2][6]); o[2][7]=fmaf(p2,v1.w,o[2][7]);
            o[3][0]=fmaf(p3,v0.x,o[3][0]); o[3][1]=fmaf(p3,v0.y,o[3][1]);
            o[3][2]=fmaf(p3,v0.z,o[3][2]); o[3][3]=fmaf(p3,v0.w,o[3][3]);
            o[3][4]=fmaf(p3,v1.x,o[3][4]); o[3][5]=fmaf(p3,v1.y,o[3][5]);
            o[3][6]=fmaf(p3,v1.z,o[3][6]); o[3][7]=fmaf(p3,v1.w,o[3][7]);
        }
    }

#pragma unroll
    for (int r = 0; r < 4; r++) {
        float inv = 1.0f / l[r];
        float* dst = out + (size_t)(b*SEQ + q0 + ty*4 + r) * HID + h*HDIM + tx*8;
        float4 w0 = make_float4(o[r][0]*inv, o[r][1]*inv, o[r][2]*inv, o[r][3]*inv);
        float4 w1 = make_float4(o[r][4]*inv, o[r][5]*inv, o[r][6]*inv, o[r][7]*inv);
        *(float4*)(dst)     = w0;
        *(float4*)(dst + 4) = w1;
    }
}

// ---------------------------------------------------------------------------
// Launch
// ---------------------------------------------------------------------------
extern "C" void kernel_launch(void* const* d_in, const int* in_sizes, int n_in,
                              void* d_out, int out_size)
{
    const float* hidden = (const float*)d_in[0];   // [2,1024,5120]
    const float* W_pack = (const float*)d_in[1];   // [15360,5120]
    const float* W_o    = (const float*)d_in[2];   // [5120,5120]
    const float* mask   = (const float*)d_in[3];   // [40,1024,1024]
    float* out = (float*)d_out;                    // [2,1024,5120]

    float *qkv, *attn;
    __nv_bfloat16 *hh, *hl, *ah, *al, *wph, *wpl, *woh, *wol;
    cudaGetSymbolAddress((void**)&qkv,  g_qkv);
    cudaGetSymbolAddress((void**)&attn, g_attn);
    cudaGetSymbolAddress((void**)&hh,  g_hh);
    cudaGetSymbolAddress((void**)&hl,  g_hl);
    cudaGetSymbolAddress((void**)&ah,  g_ah);
    cudaGetSymbolAddress((void**)&al,  g_al);
    cudaGetSymbolAddress((void**)&wph, g_wph);
    cudaGetSymbolAddress((void**)&wpl, g_wpl);
    cudaGetSymbolAddress((void**)&woh, g_woh);
    cudaGetSymbolAddress((void**)&wol, g_wol);

    cudaFuncSetAttribute(gemm_hmma, cudaFuncAttributeMaxDynamicSharedMemorySize,
                         GEMM_SMEM_BYTES);
    cudaFuncSetAttribute(attn_kernel, cudaFuncAttributeMaxDynamicSharedMemorySize,
                         ATTN_SMEM_BYTES);

    // bf16 hi/lo splits
    {
        size_t n4;
        n4 = (size_t)QKV_N * HID / 4;
        split_bf16<<<(unsigned)((n4 + 255) / 256), 256>>>(W_pack, wph, wpl, n4);
        n4 = (size_t)HID * HID / 4;
        split_bf16<<<(unsigned)((n4 + 255) / 256), 256>>>(W_o, woh, wol, n4);
        n4 = (size_t)MROWS * HID / 4;
        split_bf16<<<(unsigned)((n4 + 255) / 256), 256>>>(hidden, hh, hl, n4);
    }

    // GEMM1: qkv[2048,15360] = hidden @ W_pack^T
    gemm_hmma<<<dim3(MROWS/BM, QKV_N/BN), GTHREADS, GEMM_SMEM_BYTES>>>(
        hh, hl, wph, wpl, qkv, MROWS, QKV_N, HID);

    // Attention
    attn_kernel<<<dim3(SEQ/QT, NHEAD, BATCH), 256, ATTN_SMEM_BYTES>>>(qkv, mask, attn);

    // split attention output for GEMM2
    {
        size_t n4 = (size_t)MROWS * HID / 4;
        split_bf16<<<(unsigned)((n4 + 255) / 256), 256>>>(attn, ah, al, n4);
    }

    // GEMM2: out[2048,5120] = attn @ W_o^T
    gemm_hmma<<<dim3(MROWS/BM, HID/BN), GTHREADS, GEMM_SMEM_BYTES>>>(
        ah, al, woh, wol, out, MROWS, HID, HID);
}

// round 6
// speedup vs baseline: 2.1293x; 1.0151x over previous
#include <cuda_runtime.h>
#include <cuda_bf16.h>
#include <math.h>
#include <stdint.h>

// Problem constants
#define BATCH 2
#define SEQ   1024
#define HID   5120
#define NHEAD 40
#define HDIM  128
#define QKV_N (3*HID)          // 15360
#define MROWS (BATCH*SEQ)      // 2048

// ---------------------------------------------------------------------------
// Scratch
// ---------------------------------------------------------------------------
__device__ float g_qkv[(size_t)MROWS * QKV_N];   // [2048, 15360]
__device__ float g_attn[(size_t)MROWS * HID];    // [2048, 5120]
__device__ __nv_bfloat16 g_hh[(size_t)MROWS * HID];
__device__ __nv_bfloat16 g_hl[(size_t)MROWS * HID];
__device__ __nv_bfloat16 g_ah[(size_t)MROWS * HID];
__device__ __nv_bfloat16 g_al[(size_t)MROWS * HID];
__device__ __nv_bfloat16 g_wph[(size_t)QKV_N * HID];
__device__ __nv_bfloat16 g_wpl[(size_t)QKV_N * HID];
__device__ __nv_bfloat16 g_woh[(size_t)HID * HID];
__device__ __nv_bfloat16 g_wol[(size_t)HID * HID];

// ---------------------------------------------------------------------------
// PTX helpers (compute_103-safe: sm_80-era instructions only)
// ---------------------------------------------------------------------------
__device__ __forceinline__ uint32_t smem_u32(const void* p) {
    uint32_t a;
    asm("{ .reg .u64 t; cvta.to.shared.u64 t, %1; cvt.u32.u64 %0, t; }"
        : "=r"(a) : "l"(p));
    return a;
}

#define CP_ASYNC16(dst, src) \
    asm volatile("cp.async.cg.shared.global [%0], [%1], 16;" \
        :: "r"(dst), "l"(src))
#define CP_COMMIT() asm volatile("cp.async.commit_group;" ::: "memory")
#define CP_WAIT(n)  asm volatile("cp.async.wait_group %0;" :: "n"(n) : "memory")

__device__ __forceinline__ void ldm_x4(uint32_t* r, uint32_t addr) {
    asm volatile("ldmatrix.sync.aligned.m8n8.x4.shared.b16 {%0,%1,%2,%3}, [%4];"
        : "=r"(r[0]), "=r"(r[1]), "=r"(r[2]), "=r"(r[3]) : "r"(addr));
}

__device__ __forceinline__ void mma_bf16(float* d, const uint32_t* a,
                                         uint32_t b0, uint32_t b1) {
    asm volatile(
        "mma.sync.aligned.m16n8k16.row.col.f32.bf16.bf16.f32 "
        "{%0,%1,%2,%3}, {%4,%5,%6,%7}, {%8,%9}, {%0,%1,%2,%3};"
        : "+f"(d[0]), "+f"(d[1]), "+f"(d[2]), "+f"(d[3])
        : "r"(a[0]), "r"(a[1]), "r"(a[2]), "r"(a[3]), "r"(b0), "r"(b1));
}

// ---------------------------------------------------------------------------
// fp32 -> (bf16 hi, bf16 lo) split, vectorized
// ---------------------------------------------------------------------------
__global__ void split_bf16(const float* __restrict__ x,
                           __nv_bfloat16* __restrict__ hi,
                           __nv_bfloat16* __restrict__ lo, size_t n4)
{
    size_t i = (size_t)blockIdx.x * blockDim.x + threadIdx.x;
    if (i >= n4) return;
    float4 v = ((const float4*)x)[i];
    __nv_bfloat16 h0 = __float2bfloat16(v.x);
    __nv_bfloat16 h1 = __float2bfloat16(v.y);
    __nv_bfloat16 h2 = __float2bfloat16(v.z);
    __nv_bfloat16 h3 = __float2bfloat16(v.w);
    __nv_bfloat162 H0; H0.x = h0; H0.y = h1;
    __nv_bfloat162 H1; H1.x = h2; H1.y = h3;
    ((__nv_bfloat162*)hi)[2*i]   = H0;
    ((__nv_bfloat162*)hi)[2*i+1] = H1;
    __nv_bfloat162 L0, L1;
    L0.x = __float2bfloat16(v.x - __bfloat162float(h0));
    L0.y = __float2bfloat16(v.y - __bfloat162float(h1));
    L1.x = __float2bfloat16(v.z - __bfloat162float(h2));
    L1.y = __float2bfloat16(v.w - __bfloat162float(h3));
    ((__nv_bfloat162*)lo)[2*i]   = L0;
    ((__nv_bfloat162*)lo)[2*i+1] = L1;
}

// ---------------------------------------------------------------------------
// bf16x3 HMMA GEMM:  C[M,N] (fp32) = A[M,K] @ B[N,K]^T
//   C ≈ Ah·Bh + Ah·Bl + Al·Bh  (bf16 splits, fp32 register accumulate)
// CTA 128x128, 8 warps (4 M x 2 N), warp tile 32x64.
// K chunks of 64, 3-stage cp.async pipeline, ONE barrier per chunk.
// MMA issue reordered by split-term: each accumulator touched once per 16
// MMAs (no back-to-back RAW chains on the tensor pipe).
// Smem rows: 64 bf16 = 128B data, padded to 144B -> conflict-free ldmatrix.
// ---------------------------------------------------------------------------
#define BM 128
#define BN 128
#define BK 64
#define ROWB 144                     // bytes per smem row (64 bf16 + 16B pad)
#define TILEB (128 * ROWB)           // 18432 bytes per logical tile
#define STAGEB (4 * TILEB)           // Ah, Al, Bh, Bl = 73728
#define NSTAGE 3
#define GEMM_SMEM_BYTES (NSTAGE * STAGEB)   // 221184
#define GTHREADS 256

__global__ __launch_bounds__(GTHREADS, 1)
void gemm_hmma(const __nv_bfloat16* __restrict__ Ah, const __nv_bfloat16* __restrict__ Al,
               const __nv_bfloat16* __restrict__ Bh, const __nv_bfloat16* __restrict__ Bl,
               float* __restrict__ C, int M, int N, int K)
{
    extern __shared__ char smem[];
    const uint32_t sbase = smem_u32(smem);
    const int tid  = threadIdx.x;
    const int wid  = tid >> 5;
    const int lane = tid & 31;
    const int wm = wid & 3;          // 0..3 -> M offset wm*32
    const int wn = wid >> 2;         // 0..1 -> N offset wn*64
    const int m0 = blockIdx.x * BM;
    const int n0 = blockIdx.y * BN;
    const int NCH = K / BK;

    // stage loader: 4096 16B chunks, 16 per thread
    auto load_stage = [&](int s, int kc) {
        const int k0 = kc * BK;
#pragma unroll
        for (int j = 0; j < 16; j++) {
            int id   = tid + j * GTHREADS;   // 0..4095
            int tile = id >> 10;             // 0=Ah 1=Al 2=Bh 3=Bl
            int idx  = id & 1023;
            int row  = idx >> 3;             // 0..127
            int c16  = idx & 7;              // 0..7 (8 x 16B per 128B row)
            const __nv_bfloat16* sb =
                (tile == 0) ? Ah : (tile == 1) ? Al : (tile == 2) ? Bh : Bl;
            int grow = ((tile < 2) ? m0 : n0) + row;
            const void* src = sb + (size_t)grow * K + k0 + c16 * 8;
            uint32_t dst = sbase + s * STAGEB + tile * TILEB + row * ROWB + c16 * 16;
            CP_ASYNC16(dst, src);
        }
        CP_COMMIT();
    };

    float acc[2][8][4];
#pragma unroll
    for (int mi = 0; mi < 2; mi++)
#pragma unroll
        for (int nj = 0; nj < 8; nj++)
#pragma unroll
            for (int q = 0; q < 4; q++) acc[mi][nj][q] = 0.f;

    load_stage(0, 0);
    if (NCH > 1) load_stage(1, 1);

    const int lr = lane & 15;            // ldmatrix row within 16
    const int lc = (lane >> 4) * 16;     // byte offset of 8-col group

    // per-warp smem row bases (k-independent parts)
    const uint32_t rowA = (wm * 32 + lr) * ROWB + lc;
    const uint32_t rowB = (wn * 64 + lr) * ROWB + lc;

    int sidx = 0;   // stage of chunk c

    for (int c = 0; c < NCH; c++) {
        CP_WAIT(1);
        __syncthreads();

        // issue loads for chunk c+2 into stage (c+2)%3 == stage of chunk c-1,
        // which all warps finished before this barrier.
        if (c + 2 < NCH) {
            int s2 = sidx + 2; if (s2 >= NSTAGE) s2 -= NSTAGE;
            load_stage(s2, c + 2);
        }

        const uint32_t st  = sbase + sidx * STAGEB;
        const uint32_t sAh = st;
        const uint32_t sAl = st + TILEB;
        const uint32_t sBh = st + 2 * TILEB;
        const uint32_t sBl = st + 3 * TILEB;

#pragma unroll
        for (int kk = 0; kk < 4; kk++) {
            const uint32_t koff = kk * 32;
            uint32_t ahf[2][4], alf[2][4], bhf[4][4], blf[4][4];
#pragma unroll
            for (int mi = 0; mi < 2; mi++) {
                uint32_t ra = rowA + mi * 16 * ROWB + koff;
                ldm_x4(ahf[mi], sAh + ra);
                ldm_x4(alf[mi], sAl + ra);
            }
#pragma unroll
            for (int nj = 0; nj < 4; nj++) {
                uint32_t rb = rowB + nj * 16 * ROWB + koff;
                ldm_x4(bhf[nj], sBh + rb);
                ldm_x4(blf[nj], sBl + rb);
            }
            // term 1: Ah * Bh  (16 independent MMAs)
#pragma unroll
            for (int mi = 0; mi < 2; mi++)
#pragma unroll
                for (int nj = 0; nj < 4; nj++) {
                    mma_bf16(acc[mi][2*nj],   ahf[mi], bhf[nj][0], bhf[nj][2]);
                    mma_bf16(acc[mi][2*nj+1], ahf[mi], bhf[nj][1], bhf[nj][3]);
                }
            // term 2: Ah * Bl
#pragma unroll
            for (int mi = 0; mi < 2; mi++)
#pragma unroll
                for (int nj = 0; nj < 4; nj++) {
                    mma_bf16(acc[mi][2*nj],   ahf[mi], blf[nj][0], blf[nj][2]);
                    mma_bf16(acc[mi][2*nj+1], ahf[mi], blf[nj][1], blf[nj][3]);
                }
            // term 3: Al * Bh
#pragma unroll
            for (int mi = 0; mi < 2; mi++)
#pragma unroll
                for (int nj = 0; nj < 4; nj++) {
                    mma_bf16(acc[mi][2*nj],   alf[mi], bhf[nj][0], bhf[nj][2]);
                    mma_bf16(acc[mi][2*nj+1], alf[mi], bhf[nj][1], bhf[nj][3]);
                }
        }

        if (++sidx >= NSTAGE) sidx -= NSTAGE;
    }

    // epilogue: mma d-fragment layout
    const int g  = lane >> 2;
    const int cc = (lane & 3) * 2;
#pragma unroll
    for (int mi = 0; mi < 2; mi++) {
        const int rbase = m0 + wm * 32 + mi * 16;
#pragma unroll
        for (int nj = 0; nj < 8; nj++) {
            const int cbase = n0 + wn * 64 + nj * 8 + cc;
            float2 v0 = make_float2(acc[mi][nj][0], acc[mi][nj][1]);
            float2 v1 = make_float2(acc[mi][nj][2], acc[mi][nj][3]);
            *(float2*)&C[(size_t)(rbase + g) * N + cbase]     = v0;
            *(float2*)&C[(size_t)(rbase + g + 8) * N + cbase] = v1;
        }
    }
}

// ---------------------------------------------------------------------------
// Flash-style attention, fp32 (unchanged — passes at 4e-6)
// ---------------------------------------------------------------------------
#define QT 64
#define KT 64
#define DSTR 132
#define PSTR 68
#define ATTN_SMEM_FLOATS (3*QT*DSTR + QT*PSTR)
#define ATTN_SMEM_BYTES  (ATTN_SMEM_FLOATS * 4)

__global__ __launch_bounds__(256)
void attn_kernel(const float* __restrict__ qkv, const float* __restrict__ mask,
                 float* __restrict__ out)
{
    const int qt = blockIdx.x;
    const int h  = blockIdx.y;
    const int b  = blockIdx.z;

    extern __shared__ float sm[];
    float* q_s = sm;
    float* k_s = q_s + QT * DSTR;
    float* v_s = k_s + QT * DSTR;
    float* p_s = v_s + QT * DSTR;

    const int tid = threadIdx.x;
    const int tx = tid & 15;
    const int ty = tid >> 4;
    const int q0 = qt * QT;

    const size_t qkv_stride = QKV_N;
    const float scale = 0.08838834764831845f;

#pragma unroll
    for (int i = 0; i < 8; i++) {
        int f = tid + i * 256;
        int row = f >> 5;
        int c4  = f & 31;
        const float* src = qkv + (size_t)(b*SEQ + q0 + row) * qkv_stride + h*HDIM + c4*4;
        *(float4*)&q_s[row*DSTR + c4*4] = *(const float4*)src;
    }

    float m[4], l[4], o[4][8];
#pragma unroll
    for (int r = 0; r < 4; r++) {
        m[r] = -INFINITY; l[r] = 0.f;
#pragma unroll
        for (int c = 0; c < 8; c++) o[r][c] = 0.f;
    }

    for (int kt = 0; kt <= qt; kt++) {
        const int k0 = kt * KT;
        __syncthreads();

#pragma unroll
        for (int i = 0; i < 8; i++) {
            int f = tid + i * 256;
            int row = f >> 5;
            int c4  = f & 31;
            const float* ksrc = qkv + (size_t)(b*SEQ + k0 + row) * qkv_stride + HID   + h*HDIM + c4*4;
            const float* vsrc = qkv + (size_t)(b*SEQ + k0 + row) * qkv_stride + 2*HID + h*HDIM + c4*4;
            *(float4*)&k_s[row*DSTR + c4*4] = *(const float4*)ksrc;
            *(float4*)&v_s[row*DSTR + c4*4] = *(const float4*)vsrc;
        }
        __syncthreads();

        float sacc[4][4];
#pragma unroll
        for (int r = 0; r < 4; r++)
#pragma unroll
            for (int c = 0; c < 4; c++) sacc[r][c] = 0.f;

        for (int d = 0; d < HDIM; d += 4) {
            float4 a[4], bb[4];
#pragma unroll
            for (int r = 0; r < 4; r++) a[r]  = *(const float4*)&q_s[(ty*4+r)*DSTR + d];
#pragma unroll
            for (int c = 0; c < 4; c++) bb[c] = *(const float4*)&k_s[(tx*4+c)*DSTR + d];
#pragma unroll
            for (int r = 0; r < 4; r++)
#pragma unroll
                for (int c = 0; c < 4; c++) {
                    sacc[r][c] = fmaf(a[r].x, bb[c].x, sacc[r][c]);
                    sacc[r][c] = fmaf(a[r].y, bb[c].y, sacc[r][c]);
                    sacc[r][c] = fmaf(a[r].z, bb[c].z, sacc[r][c]);
                    sacc[r][c] = fmaf(a[r].w, bb[c].w, sacc[r][c]);
                }
        }

#pragma unroll
        for (int r = 0; r < 4; r++) {
            const int qrow = q0 + ty*4 + r;
            const float* mrow = mask + ((size_t)h * SEQ + qrow) * SEQ + k0 + tx*4;
            float4 mk = *(const float4*)mrow;
            float s0 = sacc[r][0]*scale + mk.x;
            float s1 = sacc[r][1]*scale + mk.y;
            float s2 = sacc[r][2]*scale + mk.z;
            float s3 = sacc[r][3]*scale + mk.w;
            s0 = fmaxf(s0, -3.3e38f); s1 = fmaxf(s1, -3.3e38f);
            s2 = fmaxf(s2, -3.3e38f); s3 = fmaxf(s3, -3.3e38f);

            float rm = fmaxf(fmaxf(s0, s1), fmaxf(s2, s3));
#pragma unroll
            for (int off = 8; off >= 1; off >>= 1)
                rm = fmaxf(rm, __shfl_xor_sync(0xffffffffu, rm, off, 16));

            float mn = fmaxf(m[r], rm);
            float alpha = __expf(m[r] - mn);

            float p0 = __expf(s0 - mn);
            float p1 = __expf(s1 - mn);
            float p2 = __expf(s2 - mn);
            float p3 = __expf(s3 - mn);
            float* prow = &p_s[(ty*4+r)*PSTR + tx*4];
            prow[0] = p0; prow[1] = p1; prow[2] = p2; prow[3] = p3;

            float ps = p0 + p1 + p2 + p3;
#pragma unroll
            for (int off = 8; off >= 1; off >>= 1)
                ps += __shfl_xor_sync(0xffffffffu, ps, off, 16);

            l[r] = l[r] * alpha + ps;
            m[r] = mn;
#pragma unroll
            for (int c = 0; c < 8; c++) o[r][c] *= alpha;
        }
        __syncthreads();

        for (int j = 0; j < KT; j++) {
            float p0 = p_s[(ty*4+0)*PSTR + j];
            float p1 = p_s[(ty*4+1)*PSTR + j];
            float p2 = p_s[(ty*4+2)*PSTR + j];
            float p3 = p_s[(ty*4+3)*PSTR + j];
            float4 v0 = *(const float4*)&v_s[j*DSTR + tx*8];
            float4 v1 = *(const float4*)&v_s[j*DSTR + tx*8 + 4];
            o[0][0]=fmaf(p0,v0.x,o[0][0]); o[0][1]=fmaf(p0,v0.y,o[0][1]);
            o[0][2]=fmaf(p0,v0.z,o[0][2]); o[0][3]=fmaf(p0,v0.w,o[0][3]);
            o[0][4]=fmaf(p0,v1.x,o[0][4]); o[0][5]=fmaf(p0,v1.y,o[0][5]);
            o[0][6]=fmaf(p0,v1.z,o[0][6]); o[0][7]=fmaf(p0,v1.w,o[0][7]);
            o[1][0]=fmaf(p1,v0.x,o[1][0]); o[1][1]=fmaf(p1,v0.y,o[1][1]);
            o[1][2]=fmaf(p1,v0.z,o[1][2]); o[1][3]=fmaf(p1,v0.w,o[1][3]);
            o[1][4]=fmaf(p1,v1.x,o[1][4]); o[1][5]=fmaf(p1,v1.y,o[1][5]);
            o[1][6]=fmaf(p1,v1.z,o[1][6]); o[1][7]=fmaf(p1,v1.w,o[1][7]);
            o[2][0]=fmaf(p2,v0.x,o[2][0]); o[2][1]=fmaf(p2,v0.y,o[2][1]);
            o[2][2]=fmaf(p2,v0.z,o[2][2]); o[2][3]=fmaf(p2,v0.w,o[2][3]);
            o[2][4]=fmaf(p2,v1.x,o[2][4]); o[2][5]=fmaf(p2,v1.y,o[2][5]);
            o[2][6]=fmaf(p2,v1.z,o[2][6]); o[2][7]=fmaf(p2,v1.w,o[2][7]);
            o[3][0]=fmaf(p3,v0.x,o[3][0]); o[3][1]=fmaf(p3,v0.y,o[3][1]);
            o[3][2]=fmaf(p3,v0.z,o[3][2]); o[3][3]=fmaf(p3,v0.w,o[3][3]);
            o[3][4]=fmaf(p3,v1.x,o[3][4]); o[3][5]=fmaf(p3,v1.y,o[3][5]);
            o[3][6]=fmaf(p3,v1.z,o[3][6]); o[3][7]=fmaf(p3,v1.w,o[3][7]);
        }
    }

#pragma unroll
    for (int r = 0; r < 4; r++) {
        float inv = 1.0f / l[r];
        float* dst = out + (size_t)(b*SEQ + q0 + ty*4 + r) * HID + h*HDIM + tx*8;
        float4 w0 = make_float4(o[r][0]*inv, o[r][1]*inv, o[r][2]*inv, o[r][3]*inv);
        float4 w1 = make_float4(o[r][4]*inv, o[r][5]*inv, o[r][6]*inv, o[r][7]*inv);
        *(float4*)(dst)     = w0;
        *(float4*)(dst + 4) = w1;
    }
}

// ---------------------------------------------------------------------------
// Launch
// ---------------------------------------------------------------------------
extern "C" void kernel_launch(void* const* d_in, const int* in_sizes, int n_in,
                              void* d_out, int out_size)
{
    const float* hidden = (const float*)d_in[0];   // [2,1024,5120]
    const float* W_pack = (const float*)d_in[1];   // [15360,5120]
    const float* W_o    = (const float*)d_in[2];   // [5120,5120]
    const float* mask   = (const float*)d_in[3];   // [40,1024,1024]
    float* out = (float*)d_out;                    // [2,1024,5120]

    float *qkv, *attn;
    __nv_bfloat16 *hh, *hl, *ah, *al, *wph, *wpl, *woh, *wol;
    cudaGetSymbolAddress((void**)&qkv,  g_qkv);
    cudaGetSymbolAddress((void**)&attn, g_attn);
    cudaGetSymbolAddress((void**)&hh,  g_hh);
    cudaGetSymbolAddress((void**)&hl,  g_hl);
    cudaGetSymbolAddress((void**)&ah,  g_ah);
    cudaGetSymbolAddress((void**)&al,  g_al);
    cudaGetSymbolAddress((void**)&wph, g_wph);
    cudaGetSymbolAddress((void**)&wpl, g_wpl);
    cudaGetSymbolAddress((void**)&woh, g_woh);
    cudaGetSymbolAddress((void**)&wol, g_wol);

    cudaFuncSetAttribute(gemm_hmma, cudaFuncAttributeMaxDynamicSharedMemorySize,
                         GEMM_SMEM_BYTES);
    cudaFuncSetAttribute(attn_kernel, cudaFuncAttributeMaxDynamicSharedMemorySize,
                         ATTN_SMEM_BYTES);

    // bf16 hi/lo splits
    {
        size_t n4;
        n4 = (size_t)QKV_N * HID / 4;
        split_bf16<<<(unsigned)((n4 + 255) / 256), 256>>>(W_pack, wph, wpl, n4);
        n4 = (size_t)HID * HID / 4;
        split_bf16<<<(unsigned)((n4 + 255) / 256), 256>>>(W_o, woh, wol, n4);
        n4 = (size_t)MROWS * HID / 4;
        split_bf16<<<(unsigned)((n4 + 255) / 256), 256>>>(hidden, hh, hl, n4);
    }

    // GEMM1: qkv[2048,15360] = hidden @ W_pack^T
    gemm_hmma<<<dim3(MROWS/BM, QKV_N/BN), GTHREADS, GEMM_SMEM_BYTES>>>(
        hh, hl, wph, wpl, qkv, MROWS, QKV_N, HID);

    // Attention
    attn_kernel<<<dim3(SEQ/QT, NHEAD, BATCH), 256, ATTN_SMEM_BYTES>>>(qkv, mask, attn);

    // split attention output for GEMM2
    {
        size_t n4 = (size_t)MROWS * HID / 4;
        split_bf16<<<(unsigned)((n4 + 255) / 256), 256>>>(attn, ah, al, n4);
    }

    // GEMM2: out[2048,5120] = attn @ W_o^T
    gemm_hmma<<<dim3(MROWS/BM, HID/BN), GTHREADS, GEMM_SMEM_BYTES>>>(
        ah, al, woh, wol, out, MROWS, HID, HID);
}

// round 7
// speedup vs baseline: 2.6211x; 1.2310x over previous
#include <cuda_runtime.h>
#include <cuda_bf16.h>
#include <math.h>
#include <stdint.h>

// Problem constants
#define BATCH 2
#define SEQ   1024
#define HID   5120
#define NHEAD 40
#define HDIM  128
#define QKV_N (3*HID)          // 15360
#define MROWS (BATCH*SEQ)      // 2048

// ---------------------------------------------------------------------------
// Scratch
// ---------------------------------------------------------------------------
__device__ __nv_bfloat16 g_qkvh[(size_t)MROWS * QKV_N];  // qkv split hi
__device__ __nv_bfloat16 g_qkvl[(size_t)MROWS * QKV_N];  // qkv split lo
__device__ __nv_bfloat16 g_hh[(size_t)MROWS * HID];
__device__ __nv_bfloat16 g_hl[(size_t)MROWS * HID];
__device__ __nv_bfloat16 g_ah[(size_t)MROWS * HID];
__device__ __nv_bfloat16 g_al[(size_t)MROWS * HID];
__device__ __nv_bfloat16 g_wph[(size_t)QKV_N * HID];
__device__ __nv_bfloat16 g_wpl[(size_t)QKV_N * HID];
__device__ __nv_bfloat16 g_woh[(size_t)HID * HID];
__device__ __nv_bfloat16 g_wol[(size_t)HID * HID];

// ---------------------------------------------------------------------------
// PTX helpers (compute_103-safe: sm_80-era instructions only)
// ---------------------------------------------------------------------------
__device__ __forceinline__ uint32_t smem_u32(const void* p) {
    uint32_t a;
    asm("{ .reg .u64 t; cvta.to.shared.u64 t, %1; cvt.u32.u64 %0, t; }"
        : "=r"(a) : "l"(p));
    return a;
}

#define CP_ASYNC16(dst, src) \
    asm volatile("cp.async.cg.shared.global [%0], [%1], 16;" \
        :: "r"(dst), "l"(src))
#define CP_COMMIT() asm volatile("cp.async.commit_group;" ::: "memory")
#define CP_WAIT(n)  asm volatile("cp.async.wait_group %0;" :: "n"(n) : "memory")

__device__ __forceinline__ void ldm_x4(uint32_t* r, uint32_t addr) {
    asm volatile("ldmatrix.sync.aligned.m8n8.x4.shared.b16 {%0,%1,%2,%3}, [%4];"
        : "=r"(r[0]), "=r"(r[1]), "=r"(r[2]), "=r"(r[3]) : "r"(addr));
}
__device__ __forceinline__ void ldm_x4_t(uint32_t* r, uint32_t addr) {
    asm volatile("ldmatrix.sync.aligned.m8n8.x4.trans.shared.b16 {%0,%1,%2,%3}, [%4];"
        : "=r"(r[0]), "=r"(r[1]), "=r"(r[2]), "=r"(r[3]) : "r"(addr));
}

__device__ __forceinline__ void mma_bf16(float* d, const uint32_t* a,
                                         uint32_t b0, uint32_t b1) {
    asm volatile(
        "mma.sync.aligned.m16n8k16.row.col.f32.bf16.bf16.f32 "
        "{%0,%1,%2,%3}, {%4,%5,%6,%7}, {%8,%9}, {%0,%1,%2,%3};"
        : "+f"(d[0]), "+f"(d[1]), "+f"(d[2]), "+f"(d[3])
        : "r"(a[0]), "r"(a[1]), "r"(a[2]), "r"(a[3]), "r"(b0), "r"(b1));
}

// ---------------------------------------------------------------------------
// fp32 -> (bf16 hi, bf16 lo) split, vectorized
// ---------------------------------------------------------------------------
__global__ void split_bf16(const float* __restrict__ x,
                           __nv_bfloat16* __restrict__ hi,
                           __nv_bfloat16* __restrict__ lo, size_t n4)
{
    size_t i = (size_t)blockIdx.x * blockDim.x + threadIdx.x;
    if (i >= n4) return;
    float4 v = ((const float4*)x)[i];
    __nv_bfloat16 h0 = __float2bfloat16(v.x);
    __nv_bfloat16 h1 = __float2bfloat16(v.y);
    __nv_bfloat16 h2 = __float2bfloat16(v.z);
    __nv_bfloat16 h3 = __float2bfloat16(v.w);
    __nv_bfloat162 H0; H0.x = h0; H0.y = h1;
    __nv_bfloat162 H1; H1.x = h2; H1.y = h3;
    ((__nv_bfloat162*)hi)[2*i]   = H0;
    ((__nv_bfloat162*)hi)[2*i+1] = H1;
    __nv_bfloat162 L0, L1;
    L0.x = __float2bfloat16(v.x - __bfloat162float(h0));
    L0.y = __float2bfloat16(v.y - __bfloat162float(h1));
    L1.x = __float2bfloat16(v.z - __bfloat162float(h2));
    L1.y = __float2bfloat16(v.w - __bfloat162float(h3));
    ((__nv_bfloat162*)lo)[2*i]   = L0;
    ((__nv_bfloat162*)lo)[2*i+1] = L1;
}

// ---------------------------------------------------------------------------
// bf16x3 HMMA GEMM:  C = A @ B^T   (round-6 mainloop; optional split output)
// If Cf != nullptr -> write fp32. Else write bf16 hi/lo split to Ch/Cl.
// ---------------------------------------------------------------------------
#define BM 128
#define BN 128
#define BK 64
#define ROWB 144
#define TILEB (128 * ROWB)
#define STAGEB (4 * TILEB)
#define NSTAGE 3
#define GEMM_SMEM_BYTES (NSTAGE * STAGEB)   // 221184
#define GTHREADS 256

__global__ __launch_bounds__(GTHREADS, 1)
void gemm_hmma(const __nv_bfloat16* __restrict__ Ah, const __nv_bfloat16* __restrict__ Al,
               const __nv_bfloat16* __restrict__ Bh, const __nv_bfloat16* __restrict__ Bl,
               float* __restrict__ Cf,
               __nv_bfloat16* __restrict__ Ch, __nv_bfloat16* __restrict__ Cl,
               int M, int N, int K)
{
    extern __shared__ char smem[];
    const uint32_t sbase = smem_u32(smem);
    const int tid  = threadIdx.x;
    const int wid  = tid >> 5;
    const int lane = tid & 31;
    const int wm = wid & 3;
    const int wn = wid >> 2;
    const int m0 = blockIdx.x * BM;
    const int n0 = blockIdx.y * BN;
    const int NCH = K / BK;

    auto load_stage = [&](int s, int kc) {
        const int k0 = kc * BK;
#pragma unroll
        for (int j = 0; j < 16; j++) {
            int id   = tid + j * GTHREADS;
            int tile = id >> 10;
            int idx  = id & 1023;
            int row  = idx >> 3;
            int c16  = idx & 7;
            const __nv_bfloat16* sb =
                (tile == 0) ? Ah : (tile == 1) ? Al : (tile == 2) ? Bh : Bl;
            int grow = ((tile < 2) ? m0 : n0) + row;
            const void* src = sb + (size_t)grow * K + k0 + c16 * 8;
            uint32_t dst = sbase + s * STAGEB + tile * TILEB + row * ROWB + c16 * 16;
            CP_ASYNC16(dst, src);
        }
        CP_COMMIT();
    };

    float acc[2][8][4];
#pragma unroll
    for (int mi = 0; mi < 2; mi++)
#pragma unroll
        for (int nj = 0; nj < 8; nj++)
#pragma unroll
            for (int q = 0; q < 4; q++) acc[mi][nj][q] = 0.f;

    load_stage(0, 0);
    if (NCH > 1) load_stage(1, 1);

    const int lr = lane & 15;
    const int lc = (lane >> 4) * 16;
    const uint32_t rowA = (wm * 32 + lr) * ROWB + lc;
    const uint32_t rowB = (wn * 64 + lr) * ROWB + lc;

    int sidx = 0;
    for (int c = 0; c < NCH; c++) {
        CP_WAIT(1);
        __syncthreads();
        if (c + 2 < NCH) {
            int s2 = sidx + 2; if (s2 >= NSTAGE) s2 -= NSTAGE;
            load_stage(s2, c + 2);
        }

        const uint32_t st  = sbase + sidx * STAGEB;
        const uint32_t sAh = st;
        const uint32_t sAl = st + TILEB;
        const uint32_t sBh = st + 2 * TILEB;
        const uint32_t sBl = st + 3 * TILEB;

#pragma unroll
        for (int kk = 0; kk < 4; kk++) {
            const uint32_t koff = kk * 32;
            uint32_t ahf[2][4], alf[2][4], bhf[4][4], blf[4][4];
#pragma unroll
            for (int mi = 0; mi < 2; mi++) {
                uint32_t ra = rowA + mi * 16 * ROWB + koff;
                ldm_x4(ahf[mi], sAh + ra);
                ldm_x4(alf[mi], sAl + ra);
            }
#pragma unroll
            for (int nj = 0; nj < 4; nj++) {
                uint32_t rb = rowB + nj * 16 * ROWB + koff;
                ldm_x4(bhf[nj], sBh + rb);
                ldm_x4(blf[nj], sBl + rb);
            }
#pragma unroll
            for (int mi = 0; mi < 2; mi++)
#pragma unroll
                for (int nj = 0; nj < 4; nj++) {
                    mma_bf16(acc[mi][2*nj],   ahf[mi], bhf[nj][0], bhf[nj][2]);
                    mma_bf16(acc[mi][2*nj+1], ahf[mi], bhf[nj][1], bhf[nj][3]);
                }
#pragma unroll
            for (int mi = 0; mi < 2; mi++)
#pragma unroll
                for (int nj = 0; nj < 4; nj++) {
                    mma_bf16(acc[mi][2*nj],   ahf[mi], blf[nj][0], blf[nj][2]);
                    mma_bf16(acc[mi][2*nj+1], ahf[mi], blf[nj][1], blf[nj][3]);
                }
#pragma unroll
            for (int mi = 0; mi < 2; mi++)
#pragma unroll
                for (int nj = 0; nj < 4; nj++) {
                    mma_bf16(acc[mi][2*nj],   alf[mi], bhf[nj][0], bhf[nj][2]);
                    mma_bf16(acc[mi][2*nj+1], alf[mi], bhf[nj][1], bhf[nj][3]);
                }
        }
        if (++sidx >= NSTAGE) sidx -= NSTAGE;
    }

    const int g  = lane >> 2;
    const int cc = (lane & 3) * 2;
#pragma unroll
    for (int mi = 0; mi < 2; mi++) {
        const int rbase = m0 + wm * 32 + mi * 16;
#pragma unroll
        for (int nj = 0; nj < 8; nj++) {
            const int cbase = n0 + wn * 64 + nj * 8 + cc;
            if (Cf) {
                float2 v0 = make_float2(acc[mi][nj][0], acc[mi][nj][1]);
                float2 v1 = make_float2(acc[mi][nj][2], acc[mi][nj][3]);
                *(float2*)&Cf[(size_t)(rbase + g) * N + cbase]     = v0;
                *(float2*)&Cf[(size_t)(rbase + g + 8) * N + cbase] = v1;
            } else {
#pragma unroll
                for (int rr = 0; rr < 2; rr++) {
                    float x0 = acc[mi][nj][2*rr], x1 = acc[mi][nj][2*rr+1];
                    __nv_bfloat16 h0 = __float2bfloat16(x0);
                    __nv_bfloat16 h1 = __float2bfloat16(x1);
                    __nv_bfloat162 H; H.x = h0; H.y = h1;
                    __nv_bfloat162 L;
                    L.x = __float2bfloat16(x0 - __bfloat162float(h0));
                    L.y = __float2bfloat16(x1 - __bfloat162float(h1));
                    size_t off = (size_t)(rbase + g + 8*rr) * N + cbase;
                    *(__nv_bfloat162*)&Ch[off] = H;
                    *(__nv_bfloat162*)&Cl[off] = L;
                }
            }
        }
    }
}

// ---------------------------------------------------------------------------
// HMMA flash attention, bf16x3 QK and PV, computed ALiBi, causal.
// CTA: 4 warps, 64 q-rows (16/warp), K/V tiles 64 rows, double-buffered.
// Consumes qkv hi/lo splits; writes output as bf16 hi/lo for GEMM2.
// ---------------------------------------------------------------------------
#define AROW 272                       // 128 bf16 = 256B + 16B pad
#define ATILE (64 * AROW)              // 17408
#define PROW 144                       // 64 bf16 + pad
#define PTILE (64 * PROW)              // 9216
#define KSTAGE (4 * ATILE)             // kh,kl,vh,vl = 69632
#define ATTN_SMEM (2*ATILE + 2*KSTAGE + 2*PTILE)   // 192512

__global__ __launch_bounds__(128, 1)
void attn_hmma(const __nv_bfloat16* __restrict__ QKVh,
               const __nv_bfloat16* __restrict__ QKVl,
               __nv_bfloat16* __restrict__ Oh,
               __nv_bfloat16* __restrict__ Ol)
{
    extern __shared__ char smem[];
    const uint32_t sb = smem_u32(smem);
    const int tid = threadIdx.x, wid = tid >> 5, lane = tid & 31;
    const int qt = blockIdx.x, h = blockIdx.y, b = blockIdx.z;
    const int q0 = qt * 64;
    const int lr = lane & 15, lc = (lane >> 4) * 16;
    const int g = lane >> 2, t = lane & 3;

    const uint32_t QH_ = sb, QL_ = sb + ATILE;
    const uint32_t KST = sb + 2 * ATILE;             // + s*KSTAGE
    const uint32_t PH_ = sb + 2 * ATILE + 2 * KSTAGE;
    const uint32_t PL_ = PH_ + PTILE;

    // ---- load Q (hi/lo) ----
#pragma unroll
    for (int j = 0; j < 8; j++) {
        int id = tid + j * 128;
        int row = id >> 4, c16 = id & 15;
        size_t goff = (size_t)(b * SEQ + q0 + row) * QKV_N + h * HDIM + c16 * 8;
        CP_ASYNC16(QH_ + row * AROW + c16 * 16, QKVh + goff);
        CP_ASYNC16(QL_ + row * AROW + c16 * 16, QKVl + goff);
    }
    CP_COMMIT();

    auto load_kv = [&](int s, int kt) {
        const uint32_t base = KST + s * KSTAGE;
        const int k0 = kt * 64;
#pragma unroll
        for (int j = 0; j < 8; j++) {
            int id = tid + j * 128;
            int row = id >> 4, c16 = id & 15;
            size_t grow = (size_t)(b * SEQ + k0 + row) * QKV_N;
            size_t koff = grow + HID     + h * HDIM + c16 * 8;
            size_t voff = grow + 2 * HID + h * HDIM + c16 * 8;
            uint32_t d = row * AROW + c16 * 16;
            CP_ASYNC16(base + d,             QKVh + koff);
            CP_ASYNC16(base + ATILE + d,     QKVl + koff);
            CP_ASYNC16(base + 2 * ATILE + d, QKVh + voff);
            CP_ASYNC16(base + 3 * ATILE + d, QKVl + voff);
        }
        CP_COMMIT();
    };

    load_kv(0, 0);

    const float LOG2E = 1.4426950408889634f;
    const float sscale = 0.08838834764831845f * LOG2E;   // 1/sqrt(128) * log2(e)
    const float slope = (h < 32) ? exp2f(-0.25f * (float)(h + 1))
                                 : exp2f(-0.125f * (float)(2 * (h - 32) + 1));
    const float slope2 = slope * LOG2E;

    const int row0 = q0 + wid * 16 + g;
    const int row1 = row0 + 8;

    float m0v = -1e30f, m1v = -1e30f, l0 = 0.f, l1 = 0.f;
    float o[16][4];
#pragma unroll
    for (int i = 0; i < 16; i++)
#pragma unroll
        for (int q = 0; q < 4; q++) o[i][q] = 0.f;

    for (int kt = 0; kt <= qt; kt++) {
        const bool more = (kt + 1 <= qt);
        if (more) load_kv((kt + 1) & 1, kt + 1);
        if (more) { CP_WAIT(1); } else { CP_WAIT(0); }
        __syncthreads();

        const uint32_t KB  = KST + (kt & 1) * KSTAGE;
        const uint32_t KHB = KB, KLB = KB + ATILE;
        const uint32_t VHB = KB + 2 * ATILE, VLB = KB + 3 * ATILE;

        // ---- S = Q K^T (bf16x3) ----
        float sacc[8][4];
#pragma unroll
        for (int nj = 0; nj < 8; nj++)
#pragma unroll
            for (int q = 0; q < 4; q++) sacc[nj][q] = 0.f;

#pragma unroll
        for (int dd = 0; dd < 8; dd++) {
            const uint32_t ra = (wid * 16 + lr) * AROW + dd * 32 + lc;
            uint32_t qhf[4], qlf[4];
            ldm_x4(qhf, QH_ + ra);
            ldm_x4(qlf, QL_ + ra);
            uint32_t khf[4][4], klf[4][4];
#pragma unroll
            for (int v = 0; v < 4; v++) {
                const uint32_t rb = (v * 16 + lr) * AROW + dd * 32 + lc;
                ldm_x4(khf[v], KHB + rb);
                ldm_x4(klf[v], KLB + rb);
            }
#pragma unroll
            for (int v = 0; v < 4; v++) {
                mma_bf16(sacc[2*v],   qhf, khf[v][0], khf[v][2]);
                mma_bf16(sacc[2*v+1], qhf, khf[v][1], khf[v][3]);
            }
#pragma unroll
            for (int v = 0; v < 4; v++) {
                mma_bf16(sacc[2*v],   qhf, klf[v][0], klf[v][2]);
                mma_bf16(sacc[2*v+1], qhf, klf[v][1], klf[v][3]);
            }
#pragma unroll
            for (int v = 0; v < 4; v++) {
                mma_bf16(sacc[2*v],   qlf, khf[v][0], khf[v][2]);
                mma_bf16(sacc[2*v+1], qlf, khf[v][1], khf[v][3]);
            }
        }

        // ---- softmax (log2 domain), ALiBi computed, causal on diagonal ----
        const int k0 = kt * 64;
        const bool diag = (kt == qt);
        float rmax0 = -1e30f, rmax1 = -1e30f;
#pragma unroll
        for (int nj = 0; nj < 8; nj++) {
#pragma unroll
            for (int e = 0; e < 2; e++) {
                const int col = k0 + nj * 8 + 2 * t + e;
                float v0 = sacc[nj][e]     * sscale + slope2 * (float)col;
                float v1 = sacc[nj][2 + e] * sscale + slope2 * (float)col;
                if (diag) {
                    if (col > row0) v0 = -1e30f;
                    if (col > row1) v1 = -1e30f;
                }
                sacc[nj][e] = v0; sacc[nj][2 + e] = v1;
                rmax0 = fmaxf(rmax0, v0); rmax1 = fmaxf(rmax1, v1);
            }
        }
        rmax0 = fmaxf(rmax0, __shfl_xor_sync(0xffffffffu, rmax0, 1));
        rmax0 = fmaxf(rmax0, __shfl_xor_sync(0xffffffffu, rmax0, 2));
        rmax1 = fmaxf(rmax1, __shfl_xor_sync(0xffffffffu, rmax1, 1));
        rmax1 = fmaxf(rmax1, __shfl_xor_sync(0xffffffffu, rmax1, 2));

        const float mn0 = fmaxf(m0v, rmax0), mn1 = fmaxf(m1v, rmax1);
        const float al0 = exp2f(m0v - mn0),  al1 = exp2f(m1v - mn1);
        m0v = mn0; m1v = mn1;

        float ps0 = 0.f, ps1 = 0.f;
#pragma unroll
        for (int nj = 0; nj < 8; nj++) {
#pragma unroll
            for (int e = 0; e < 2; e++) {
                float p0 = exp2f(sacc[nj][e]     - mn0);
                float p1 = exp2f(sacc[nj][2 + e] - mn1);
                sacc[nj][e] = p0; sacc[nj][2 + e] = p1;
                ps0 += p0; ps1 += p1;
            }
        }
        ps0 += __shfl_xor_sync(0xffffffffu, ps0, 1);
        ps0 += __shfl_xor_sync(0xffffffffu, ps0, 2);
        ps1 += __shfl_xor_sync(0xffffffffu, ps1, 1);
        ps1 += __shfl_xor_sync(0xffffffffu, ps1, 2);
        l0 = l0 * al0 + ps0;
        l1 = l1 * al1 + ps1;

        // rescale O
#pragma unroll
        for (int i = 0; i < 16; i++) {
            o[i][0] *= al0; o[i][1] *= al0;
            o[i][2] *= al1; o[i][3] *= al1;
        }

        // ---- write P hi/lo to smem ----
#pragma unroll
        for (int nj = 0; nj < 8; nj++) {
#pragma unroll
            for (int rr = 0; rr < 2; rr++) {
                float x0 = sacc[nj][2*rr], x1 = sacc[nj][2*rr + 1];
                __nv_bfloat16 h0 = __float2bfloat16(x0);
                __nv_bfloat16 h1 = __float2bfloat16(x1);
                __nv_bfloat162 H; H.x = h0; H.y = h1;
                __nv_bfloat162 L;
                L.x = __float2bfloat16(x0 - __bfloat162float(h0));
                L.y = __float2bfloat16(x1 - __bfloat162float(h1));
                uint32_t off = (wid * 16 + g + 8 * rr) * PROW + (nj * 8 + 2 * t) * 2;
                *(__nv_bfloat162*)(smem + (PH_ - sb) + off) = H;
                *(__nv_bfloat162*)(smem + (PL_ - sb) + off) = L;
            }
        }
        __syncwarp();

        // ---- O += P V (bf16x3) ----
#pragma unroll
        for (int ks = 0; ks < 4; ks++) {
            const uint32_t pa = (wid * 16 + lr) * PROW + ks * 32 + lc;
            uint32_t phf[4], plf[4];
            ldm_x4(phf, PH_ + pa);
            ldm_x4(plf, PL_ + pa);
#pragma unroll
            for (int nn = 0; nn < 8; nn++) {
                const uint32_t va = (ks * 16 + lr) * AROW + nn * 32 + lc;
                uint32_t vhf[4], vlf[4];
                ldm_x4_t(vhf, VHB + va);
                ldm_x4_t(vlf, VLB + va);
                mma_bf16(o[2*nn],   phf, vhf[0], vhf[1]);
                mma_bf16(o[2*nn+1], phf, vhf[2], vhf[3]);
                mma_bf16(o[2*nn],   phf, vlf[0], vlf[1]);
                mma_bf16(o[2*nn+1], phf, vlf[2], vlf[3]);
                mma_bf16(o[2*nn],   plf, vhf[0], vhf[1]);
                mma_bf16(o[2*nn+1], plf, vhf[2], vhf[3]);
            }
        }
        __syncthreads();
    }

    // ---- epilogue: normalize, split to bf16 hi/lo ----
    const float inv0 = 1.0f / l0, inv1 = 1.0f / l1;
#pragma unroll
    for (int i = 0; i < 16; i++) {
        const int col = h * HDIM + i * 8 + 2 * t;
#pragma unroll
        for (int rr = 0; rr < 2; rr++) {
            const float inv = rr ? inv1 : inv0;
            const int row = rr ? row1 : row0;
            float x0 = o[i][2*rr] * inv, x1 = o[i][2*rr + 1] * inv;
            __nv_bfloat16 h0 = __float2bfloat16(x0);
            __nv_bfloat16 h1 = __float2bfloat16(x1);
            __nv_bfloat162 H; H.x = h0; H.y = h1;
            __nv_bfloat162 L;
            L.x = __float2bfloat16(x0 - __bfloat162float(h0));
            L.y = __float2bfloat16(x1 - __bfloat162float(h1));
            size_t off = (size_t)(b * SEQ + row) * HID + col;
            *(__nv_bfloat162*)&Oh[off] = H;
            *(__nv_bfloat162*)&Ol[off] = L;
        }
    }
}

// ---------------------------------------------------------------------------
// Launch
// ---------------------------------------------------------------------------
extern "C" void kernel_launch(void* const* d_in, const int* in_sizes, int n_in,
                              void* d_out, int out_size)
{
    const float* hidden = (const float*)d_in[0];   // [2,1024,5120]
    const float* W_pack = (const float*)d_in[1];   // [15360,5120]
    const float* W_o    = (const float*)d_in[2];   // [5120,5120]
    float* out = (float*)d_out;                    // [2,1024,5120]

    __nv_bfloat16 *qkvh, *qkvl, *hh, *hl, *ah, *al, *wph, *wpl, *woh, *wol;
    cudaGetSymbolAddress((void**)&qkvh, g_qkvh);
    cudaGetSymbolAddress((void**)&qkvl, g_qkvl);
    cudaGetSymbolAddress((void**)&hh,  g_hh);
    cudaGetSymbolAddress((void**)&hl,  g_hl);
    cudaGetSymbolAddress((void**)&ah,  g_ah);
    cudaGetSymbolAddress((void**)&al,  g_al);
    cudaGetSymbolAddress((void**)&wph, g_wph);
    cudaGetSymbolAddress((void**)&wpl, g_wpl);
    cudaGetSymbolAddress((void**)&woh, g_woh);
    cudaGetSymbolAddress((void**)&wol, g_wol);

    cudaFuncSetAttribute(gemm_hmma, cudaFuncAttributeMaxDynamicSharedMemorySize,
                         GEMM_SMEM_BYTES);
    cudaFuncSetAttribute(attn_hmma, cudaFuncAttributeMaxDynamicSharedMemorySize,
                         ATTN_SMEM);

    // bf16 hi/lo splits of inputs
    {
        size_t n4;
        n4 = (size_t)QKV_N * HID / 4;
        split_bf16<<<(unsigned)((n4 + 255) / 256), 256>>>(W_pack, wph, wpl, n4);
        n4 = (size_t)HID * HID / 4;
        split_bf16<<<(unsigned)((n4 + 255) / 256), 256>>>(W_o, woh, wol, n4);
        n4 = (size_t)MROWS * HID / 4;
        split_bf16<<<(unsigned)((n4 + 255) / 256), 256>>>(hidden, hh, hl, n4);
    }

    // GEMM1: qkv = hidden @ W_pack^T, written directly as bf16 hi/lo
    gemm_hmma<<<dim3(MROWS/BM, QKV_N/BN), GTHREADS, GEMM_SMEM_BYTES>>>(
        hh, hl, wph, wpl, nullptr, qkvh, qkvl, MROWS, QKV_N, HID);

    // Attention (HMMA flash, computed ALiBi), writes bf16 hi/lo
    attn_hmma<<<dim3(SEQ/64, NHEAD, BATCH), 128, ATTN_SMEM>>>(qkvh, qkvl, ah, al);

    // GEMM2: out = attn @ W_o^T, fp32 output
    gemm_hmma<<<dim3(MROWS/BM, HID/BN), GTHREADS, GEMM_SMEM_BYTES>>>(
        ah, al, woh, wol, out, nullptr, nullptr, MROWS, HID, HID);
}